// round 7
// baseline (speedup 1.0000x reference)
#include <cuda_runtime.h>
#include <cstdint>

// EnsKF step, all-fp32 with packed f32x2 FMA GEMMs (B300 dual-rate fp32 pipe):
//   G  = E @ H              (f32x2 SIMT GEMM, split-K)
//   Gc = G - colmean;  A = Gc^T Gc/ens + diag(std^2);  L = chol(A)
//   Dinv = inv of L's 32x32 diag blocks;  Z = A^{-1} innov (smem trisolve)
//   Mt[e][f] = (1/ens) sum_j Z[j][e] Gc[f][j]
//   out = E + Mt @ E        (f32x2 GEMM, epilogue adds E)

#define BATCH 8
#define ENSN  256
#define XDIM  8192
#define NSQ   65536
#define SPLITS 8

__device__ __align__(256) float g_part[SPLITS * BATCH * NSQ];
__device__ __align__(256) float g_G[BATCH * NSQ];
__device__ __align__(256) float g_mu[BATCH * 256];
__device__ __align__(256) float g_A[BATCH * NSQ];
__device__ __align__(256) float g_Z[BATCH * NSQ];
__device__ __align__(256) float g_Dinv[BATCH * 8 * 32 * 32];
__device__ __align__(256) float g_W[BATCH * NSQ];     // Mt [b][e][f]

typedef unsigned long long u64t;

// ---------------- packed fp32x2 helpers ----------------
__device__ __forceinline__ void fma2(u64t& c, u64t a, u64t b) {
    asm("fma.rn.f32x2 %0, %1, %2, %0;" : "+l"(c) : "l"(a), "l"(b));
}
__device__ __forceinline__ u64t dup2(float x) {
    u64t d;
    asm("mov.b64 %0, {%1, %1};" : "=l"(d) : "r"(__float_as_uint(x)));
    return d;
}
__device__ __forceinline__ float2 unp2(u64t v) {
    float2 r;
    asm("mov.b64 {%0, %1}, %2;" : "=f"(r.x), "=f"(r.y) : "l"(v));
    return r;
}
__device__ __forceinline__ uint32_t smem_u32(const void* p) {
    uint32_t a;
    asm("{ .reg .u64 t; cvta.to.shared.u64 t, %1; cvt.u32.u64 %0, t; }" : "=r"(a) : "l"(p));
    return a;
}
__device__ __forceinline__ void cpa8(uint32_t dst, const void* src) {
    asm volatile("cp.async.ca.shared.global [%0], [%1], 8;" :: "r"(dst), "l"(src));
}

// ---------------- GEMM smem layout (bytes) ----------------
// A[buf]: [128 m][34 fl] row stride 136B (2 ty-groups land 16 banks apart)
// B[buf]: [32 k] row stride 632B; pair p at slot p+(p>>2)  (conflict-free reads)
#define SA_OFF(buf) ((buf) * 17408)
#define SB_OFF(buf) (34816 + (buf) * 20224)
#define GSMEM 75264

// ---------------- producer: one 32-K chunk of A[128xK], B[Kx128] ----------------
__device__ __forceinline__ void issue_tiles(uint32_t sb,
                                            const float* __restrict__ A, size_t lda,
                                            const float* __restrict__ B, size_t ldb,
                                            int buf, int kbase, int tid) {
#pragma unroll
    for (int it = 0; it < 8; it++) {            // A: 2048 8B chunks
        const int c = tid + it * 256;
        const int r = c >> 4, seg = c & 15;
        cpa8(sb + SA_OFF(buf) + r * 136 + seg * 8,
             A + (size_t)r * lda + kbase + seg * 2);
    }
#pragma unroll
    for (int it = 0; it < 8; it++) {            // B: 2048 8B pairs, slot-swizzled
        const int c = tid + it * 256;
        const int k = c >> 6, p = c & 63;
        const int slot = p + (p >> 2);
        cpa8(sb + SB_OFF(buf) + k * 632 + slot * 8,
             B + (size_t)(kbase + k) * ldb + p * 2);
    }
}

// ---------------- core: C[128x128] += A[128xK] @ B[Kx128] ----------------
// 256 threads as 16(ty=m) x 16(tx=n); thread tile 8m x 8n (4 n-pairs).
__device__ __forceinline__ void gemm_core(const float* __restrict__ A, size_t lda,
                                          const float* __restrict__ B, size_t ldb,
                                          int nch, u64t acc[8][4], char* smem) {
    const uint32_t sb = smem_u32(smem);
    const int tid = threadIdx.x;
    const int tx = tid & 15, ty = tid >> 4;
#pragma unroll
    for (int i = 0; i < 8; i++)
#pragma unroll
        for (int j = 0; j < 4; j++) acc[i][j] = 0ull;

    const uint32_t aoff = sb + ty * 1088;        // + SA buf offset later
    const uint32_t boff = sb + 34816 + tx * 40;  // + SB buf offset later

    issue_tiles(sb, A, lda, B, ldb, 0, 0, tid);
    asm volatile("cp.async.commit_group;" ::: "memory");
    if (nch > 1) issue_tiles(sb, A, lda, B, ldb, 1, 32, tid);
    asm volatile("cp.async.commit_group;" ::: "memory");

    for (int c = 0; c < nch; c++) {
        asm volatile("cp.async.wait_group 1;" ::: "memory");
        __syncthreads();
        const int buf = c & 1;
        const uint32_t ab = aoff + buf * 17408;
        const uint32_t bb = boff + buf * 20224;
#pragma unroll 2
        for (int k2 = 0; k2 < 16; k2++) {
            u64t bk[2][4];
#pragma unroll
            for (int kk = 0; kk < 2; kk++)
#pragma unroll
                for (int j = 0; j < 4; j++)
                    asm("ld.shared.b64 %0, [%1];" : "=l"(bk[kk][j])
                        : "r"(bb + (k2 * 2 + kk) * 632 + j * 8));
            float2 av[8];
#pragma unroll
            for (int i = 0; i < 8; i++)
                asm("ld.shared.v2.f32 {%0, %1}, [%2];" : "=f"(av[i].x), "=f"(av[i].y)
                    : "r"(ab + i * 136 + k2 * 8));
#pragma unroll
            for (int kk = 0; kk < 2; kk++)
#pragma unroll
                for (int i = 0; i < 8; i++) {
                    const u64t ad = dup2(kk ? av[i].y : av[i].x);
                    fma2(acc[i][0], ad, bk[kk][0]);
                    fma2(acc[i][1], ad, bk[kk][1]);
                    fma2(acc[i][2], ad, bk[kk][2]);
                    fma2(acc[i][3], ad, bk[kk][3]);
                }
        }
        __syncthreads();
        if (c + 2 < nch)
            issue_tiles(sb, A, lda, B, ldb, buf, (c + 2) * 32, tid);
        asm volatile("cp.async.commit_group;" ::: "memory");
    }
}

// ---------------------------------------------------------------------------
// GEMM1: split-K partials of G = E @ H.  grid(4 = mt*2+nt, 8 splits, 8 b)
// ---------------------------------------------------------------------------
__global__ __launch_bounds__(256, 2) void k_mm1(const float* __restrict__ E,
                                                const float* __restrict__ H) {
    extern __shared__ char smem[];
    const int mt = blockIdx.x >> 1, nt = blockIdx.x & 1;
    const int s = blockIdx.y, b = blockIdx.z;
    const float* A = E + ((size_t)b * ENSN + mt * 128) * XDIM + (size_t)s * 1024;
    const float* B = H + (size_t)(s * 1024) * 256 + nt * 128;
    u64t acc[8][4];
    gemm_core(A, XDIM, B, 256, 32, acc, smem);

    float* Cp = g_part + (size_t)(s * BATCH + b) * NSQ + (mt * 128) * 256 + nt * 128;
    const int tx = threadIdx.x & 15, ty = threadIdx.x >> 4;
#pragma unroll
    for (int i = 0; i < 8; i++) {
        const int row = ty * 8 + i;
        float2 p0 = unp2(acc[i][0]), p1 = unp2(acc[i][1]);
        float2 p2 = unp2(acc[i][2]), p3 = unp2(acc[i][3]);
        *(float4*)(Cp + row * 256 + tx * 8)     = make_float4(p0.x, p0.y, p1.x, p1.y);
        *(float4*)(Cp + row * 256 + tx * 8 + 4) = make_float4(p2.x, p2.y, p3.x, p3.y);
    }
}

// ---------------------------------------------------------------------------
// GEMM3: out = E + Mt @ E.  grid(64 nt, 2 mt, 8 b)
// ---------------------------------------------------------------------------
__global__ __launch_bounds__(256, 2) void k_mm3(const float* __restrict__ E,
                                                float* __restrict__ out) {
    extern __shared__ char smem[];
    const int nt = blockIdx.x, mt = blockIdx.y, b = blockIdx.z;
    const int n0 = nt * 128;
    const float* A = g_W + (size_t)b * NSQ + (size_t)(mt * 128) * 256;
    const float* B = E + (size_t)b * ENSN * XDIM + n0;
    u64t acc[8][4];
    gemm_core(A, 256, B, XDIM, 8, acc, smem);

    const int tx = threadIdx.x & 15, ty = threadIdx.x >> 4;
    const float* Ep = E + (size_t)b * ENSN * XDIM;
    float* Op = out + (size_t)b * ENSN * XDIM;
#pragma unroll
    for (int i = 0; i < 8; i++) {
        const int e = mt * 128 + ty * 8 + i;
        const int x = n0 + tx * 8;
        float2 p0 = unp2(acc[i][0]), p1 = unp2(acc[i][1]);
        float2 p2 = unp2(acc[i][2]), p3 = unp2(acc[i][3]);
        float4 e0 = *(const float4*)(Ep + (size_t)e * XDIM + x);
        float4 e1 = *(const float4*)(Ep + (size_t)e * XDIM + x + 4);
        *(float4*)(Op + (size_t)e * XDIM + x) =
            make_float4(e0.x + p0.x, e0.y + p0.y, e0.z + p1.x, e0.w + p1.y);
        *(float4*)(Op + (size_t)e * XDIM + x + 4) =
            make_float4(e1.x + p2.x, e1.y + p2.y, e1.z + p3.x, e1.w + p3.y);
    }
}

// ---------------------------------------------------------------------------
__global__ __launch_bounds__(256) void k_reduce() {
    const int i = blockIdx.x * 256 + threadIdx.x;
    const float4* P = (const float4*)g_part;
    float4 s = P[i];
#pragma unroll
    for (int p = 1; p < SPLITS; p++) {
        float4 v = P[(size_t)p * (BATCH * NSQ / 4) + i];
        s.x += v.x; s.y += v.y; s.z += v.z; s.w += v.w;
    }
    ((float4*)g_G)[i] = s;
}

__global__ __launch_bounds__(256) void k_colmean() {
    const int b = blockIdx.y;
    const int j = blockIdx.x * 32 + (threadIdx.x & 31);
    const int er = threadIdx.x >> 5;
    const float* G = g_G + b * NSQ;
    float s = 0.0f;
    for (int e = er; e < ENSN; e += 8) s += G[e * 256 + j];
    __shared__ float red[8][32];
    red[er][threadIdx.x & 31] = s;
    __syncthreads();
    if (er == 0) {
        float t = 0.0f;
#pragma unroll
        for (int r = 0; r < 8; r++) t += red[r][threadIdx.x & 31];
        g_mu[b * 256 + j] = t * (1.0f / 256.0f);
    }
}

__global__ __launch_bounds__(256) void k_centerT(const float* __restrict__ ymean,
                                                 const float* __restrict__ ystd,
                                                 const float* __restrict__ noise) {
    const int b = blockIdx.z, j0 = blockIdx.y * 32, e0 = blockIdx.x * 32;
    float* G = g_G + b * NSQ;
    float* Z = g_Z + b * NSQ;
    const float* nz = noise + b * NSQ;
    __shared__ float T[32][33];
    const int tx = threadIdx.x & 31, ty = threadIdx.x >> 5;
    const float mu = g_mu[b * 256 + j0 + tx];
#pragma unroll
    for (int r = 0; r < 4; r++) {
        const int e = e0 + ty + r * 8;
        float gc = G[e * 256 + j0 + tx] - mu;
        G[e * 256 + j0 + tx] = gc;
        T[ty + r * 8][tx] = gc;
    }
    __syncthreads();
#pragma unroll
    for (int r = 0; r < 4; r++) {
        const int j = j0 + ty + r * 8;
        const float ym = ymean[j];
        const float sd = ystd[j];
        Z[j * 256 + e0 + tx] = ym - T[tx][ty + r * 8] + nz[j * 256 + e0 + tx] * sd * sd;
    }
}

__global__ __launch_bounds__(256) void k_cyy(const float* __restrict__ ystd) {
    const int b = blockIdx.y;
    const int u0 = (blockIdx.x >> 2) * 64, v0 = (blockIdx.x & 3) * 64;
    const float* G = g_G + b * NSQ;
    float* A = g_A + b * NSQ;
    __shared__ float Us[16][64];
    __shared__ float Vs[16][64];
    const int tx = threadIdx.x & 15, ty = threadIdx.x >> 4;
    const int lk = threadIdx.x >> 4, lc = (threadIdx.x & 15) * 4;
    float acc[4][4];
#pragma unroll
    for (int i = 0; i < 4; i++)
#pragma unroll
        for (int j = 0; j < 4; j++) acc[i][j] = 0.0f;

    for (int ee = 0; ee < 256; ee += 16) {
        *(float4*)&Us[lk][lc] = *(const float4*)&G[(ee + lk) * 256 + u0 + lc];
        *(float4*)&Vs[lk][lc] = *(const float4*)&G[(ee + lk) * 256 + v0 + lc];
        __syncthreads();
#pragma unroll
        for (int k = 0; k < 16; k++) {
            float4 u = *(float4*)&Us[k][ty * 4];
            float4 v = *(float4*)&Vs[k][tx * 4];
            float ua[4] = {u.x, u.y, u.z, u.w};
            float va[4] = {v.x, v.y, v.z, v.w};
#pragma unroll
            for (int i = 0; i < 4; i++)
#pragma unroll
                for (int j = 0; j < 4; j++) acc[i][j] = fmaf(ua[i], va[j], acc[i][j]);
        }
        __syncthreads();
    }
#pragma unroll
    for (int i = 0; i < 4; i++)
#pragma unroll
        for (int j = 0; j < 4; j++) {
            const int u = u0 + ty * 4 + i, v = v0 + tx * 4 + j;
            float val = acc[i][j] * (1.0f / 256.0f);
            if (u == v) { float sd = ystd[u]; val += sd * sd; }
            A[u * 256 + v] = val;
        }
}

__global__ __launch_bounds__(256) void k_chol() {
    const int b = blockIdx.x;
    float* a = g_A + b * NSQ;
    __shared__ float P[256][33];
    __shared__ float sD[32];
    const int tid = threadIdx.x;

    for (int kb = 0; kb < 8; kb++) {
        const int j0 = kb * 32;
        if (tid >= j0) {
#pragma unroll
            for (int c = 0; c < 32; c++) P[tid][c] = a[tid * 256 + j0 + c];
        }
        __syncthreads();
        for (int k = 0; k < 32; k++) {
            const int gk = j0 + k;
            const float piv = P[gk][k];
            const float d = sqrtf(piv);
            const float rd = 1.0f / d;
            if (tid == gk) sD[k] = d;
            if (tid > gk) P[tid][k] *= rd;
            __syncthreads();
            if (tid > gk) {
                const float lrk = P[tid][k];
#pragma unroll
                for (int c = k + 1; c < 32; c++) P[tid][c] -= lrk * P[j0 + c][k];
            }
            __syncthreads();
        }
        if (tid >= j0) {
#pragma unroll
            for (int c = 0; c < 32; c++) {
                float val = P[tid][c];
                if (tid - j0 == c) val = sD[c];
                a[tid * 256 + j0 + c] = val;
            }
        }
        __syncthreads();
        const int rem = 224 - j0;
        if (rem > 0) {
            for (int idx = tid; idx < rem * rem; idx += 256) {
                const int r = j0 + 32 + idx / rem;
                const int c = j0 + 32 + (idx - (idx / rem) * rem);
                float acc = a[r * 256 + c];
#pragma unroll
                for (int k = 0; k < 32; k++) acc -= P[r][k] * P[c][k];
                a[r * 256 + c] = acc;
            }
        }
        __syncthreads();
    }
}

__global__ void k_invdiag() {
    const int p = blockIdx.x & 7, b = blockIdx.x >> 3, j0 = p * 32;
    const float* a = g_A + b * NSQ;
    __shared__ float Ld[32][33];
    __shared__ float Xc[32][33];
    const int lane = threadIdx.x;
    for (int i = 0; i < 32; i++) Ld[i][lane] = a[(j0 + i) * 256 + j0 + lane];
    __syncwarp();
    for (int i = 0; i < 32; i++) {
        float s = (i == lane) ? 1.0f : 0.0f;
        for (int k = lane; k < i; k++) s -= Ld[i][k] * Xc[k][lane];
        Xc[i][lane] = (i >= lane) ? s / Ld[i][i] : 0.0f;
    }
    __syncwarp();
    for (int i = 0; i < 32; i++)
        g_Dinv[(b * 8 + p) * 1024 + i * 32 + lane] = Xc[i][lane];
}

#define TS_SMEM 129920
__global__ __launch_bounds__(256) void k_trisolve2() {
    extern __shared__ float sm[];
    float (*Zs)[65] = (float(*)[65])sm;
    float (*Dv)[33] = (float(*)[33])(sm + 256 * 65);
    float (*Lp)[33] = (float(*)[33])(sm + 256 * 65 + 256 * 33);
    const int b = blockIdx.y, e0 = blockIdx.x * 64;
    const float* L = g_A + b * NSQ;
    float* Z = g_Z + b * NSQ;
    const int tid = threadIdx.x, c = tid & 63, rg = tid >> 6;

    for (int idx = tid; idx < 256 * 64; idx += 256)
        Zs[idx >> 6][idx & 63] = Z[(idx >> 6) * 256 + e0 + (idx & 63)];
    for (int idx = tid; idx < 8 * 32 * 32; idx += 256)
        Dv[idx >> 5][idx & 31] = g_Dinv[b * 8192 + idx];
    __syncthreads();

    for (int p = 0; p < 8; p++) {
        const int j0 = p * 32, rem = 224 - j0;
        float w[8];
#pragma unroll
        for (int q = 0; q < 8; q++) {
            const int r = rg * 8 + q;
            float s = 0.0f;
#pragma unroll
            for (int k = 0; k < 32; k++) s = fmaf(Dv[p * 32 + r][k], Zs[j0 + k][c], s);
            w[q] = s;
        }
        for (int idx = tid; idx < rem * 32; idx += 256)
            Lp[idx >> 5][idx & 31] = L[(j0 + 32 + (idx >> 5)) * 256 + j0 + (idx & 31)];
        __syncthreads();
#pragma unroll
        for (int q = 0; q < 8; q++) Zs[j0 + rg * 8 + q][c] = w[q];
        __syncthreads();
        for (int rr = rg; rr < rem; rr += 4) {
            float acc = Zs[j0 + 32 + rr][c];
#pragma unroll
            for (int k = 0; k < 32; k++) acc = fmaf(-Lp[rr][k], Zs[j0 + k][c], acc);
            Zs[j0 + 32 + rr][c] = acc;
        }
        __syncthreads();
    }

    for (int p = 7; p >= 0; p--) {
        const int j0 = p * 32;
        float w[8];
#pragma unroll
        for (int q = 0; q < 8; q++) {
            const int k = rg * 8 + q;
            float s = 0.0f;
#pragma unroll
            for (int i = 0; i < 32; i++) s = fmaf(Dv[p * 32 + i][k], Zs[j0 + i][c], s);
            w[q] = s;
        }
        for (int idx = tid; idx < j0 * 32; idx += 256)
            Lp[idx >> 5][idx & 31] = L[(j0 + (idx & 31)) * 256 + (idx >> 5)];
        __syncthreads();
#pragma unroll
        for (int q = 0; q < 8; q++) Zs[j0 + rg * 8 + q][c] = w[q];
        __syncthreads();
        for (int t = rg; t < j0; t += 4) {
            float acc = Zs[t][c];
#pragma unroll
            for (int k = 0; k < 32; k++) acc = fmaf(-Lp[t][k], Zs[j0 + k][c], acc);
            Zs[t][c] = acc;
        }
        __syncthreads();
    }

    for (int idx = tid; idx < 256 * 64; idx += 256)
        Z[(idx >> 6) * 256 + e0 + (idx & 63)] = Zs[idx >> 6][idx & 63];
}

// Mt[e][f] = (1/ens) sum_j Z[j][e] * Gc[f][j]  -> fp32
__global__ __launch_bounds__(256) void k_wp() {
    const int b = blockIdx.y;
    const int e0 = (blockIdx.x >> 2) * 64, f0 = (blockIdx.x & 3) * 64;
    const float* G = g_G + b * NSQ;
    const float* Z = g_Z + b * NSQ;
    float* W = g_W + b * NSQ;
    __shared__ float sZ[16][64];
    __shared__ float sG[16][64];
    const int tx = threadIdx.x & 15, ty = threadIdx.x >> 4;
    const int lk = threadIdx.x >> 4, lc = (threadIdx.x & 15) * 4;
    const int gn = threadIdx.x >> 2, gk = (threadIdx.x & 3) * 4;
    float acc[4][4];
#pragma unroll
    for (int i = 0; i < 4; i++)
#pragma unroll
        for (int j = 0; j < 4; j++) acc[i][j] = 0.0f;

    for (int jj = 0; jj < 256; jj += 16) {
        *(float4*)&sZ[lk][lc] = *(const float4*)&Z[(jj + lk) * 256 + e0 + lc];
        float4 gv = *(const float4*)&G[(f0 + gn) * 256 + jj + gk];
        sG[gk + 0][gn] = gv.x; sG[gk + 1][gn] = gv.y;
        sG[gk + 2][gn] = gv.z; sG[gk + 3][gn] = gv.w;
        __syncthreads();
#pragma unroll
        for (int k = 0; k < 16; k++) {
            float4 zv = *(float4*)&sZ[k][ty * 4];
            float4 gg = *(float4*)&sG[k][tx * 4];
            float za[4] = {zv.x, zv.y, zv.z, zv.w};
            float ga[4] = {gg.x, gg.y, gg.z, gg.w};
#pragma unroll
            for (int i = 0; i < 4; i++)
#pragma unroll
                for (int j = 0; j < 4; j++) acc[i][j] = fmaf(za[i], ga[j], acc[i][j]);
        }
        __syncthreads();
    }
#pragma unroll
    for (int i = 0; i < 4; i++)
#pragma unroll
        for (int j = 0; j < 4; j++) {
            const int e = e0 + ty * 4 + i, f = f0 + tx * 4 + j;
            W[e * 256 + f] = acc[i][j] * (1.0f / 256.0f);
        }
}

// ---------------------------------------------------------------------------
extern "C" void kernel_launch(void* const* d_in, const int* in_sizes, int n_in,
                              void* d_out, int out_size) {
    const float* E     = (const float*)d_in[0];
    const float* H     = (const float*)d_in[1];
    const float* ymean = (const float*)d_in[2];
    const float* ystd  = (const float*)d_in[3];
    const float* noise = (const float*)d_in[4];
    float* out = (float*)d_out;

    cudaFuncSetAttribute(k_mm1, cudaFuncAttributeMaxDynamicSharedMemorySize, GSMEM);
    cudaFuncSetAttribute(k_mm3, cudaFuncAttributeMaxDynamicSharedMemorySize, GSMEM);
    cudaFuncSetAttribute(k_trisolve2, cudaFuncAttributeMaxDynamicSharedMemorySize, TS_SMEM);

    k_mm1<<<dim3(4, SPLITS, BATCH), 256, GSMEM>>>(E, H);
    k_reduce<<<(BATCH * NSQ / 4) / 256, 256>>>();
    k_colmean<<<dim3(8, BATCH), 256>>>();
    k_centerT<<<dim3(8, 8, BATCH), 256>>>(ymean, ystd, noise);
    k_cyy<<<dim3(16, BATCH), 256>>>(ystd);
    k_chol<<<BATCH, 256>>>();
    k_invdiag<<<64, 32>>>();
    k_trisolve2<<<dim3(4, BATCH), 256, TS_SMEM>>>();
    k_wp<<<dim3(16, BATCH), 256>>>();
    k_mm3<<<dim3(64, 2, BATCH), 256, GSMEM>>>(E, out);
}

// round 9
// speedup vs baseline: 1.2474x; 1.2474x over previous
#include <cuda_runtime.h>
#include <cuda_fp16.h>
#include <cstdint>

// EnsKF step. fp16 3-term split mma GEMMs, register-lean + 2 CTA/SM:
//   G  = E @ H          (mma.m16n8k16.f16, hh+hl+lh, split-K)
//   Gc = G - colmean;  A = Gc^T Gc/ens + diag(std^2);  L = chol(A)
//   Dinv = inv of L's 32x32 diag blocks;  Z = A^{-1} innov (smem trisolve)
//   Mt[e][f] = (1/ens) sum_j Z[j][e] Gc[f][j]  -> fp16 hi/lo
//   out = E + Mt @ E    (mma fp16 3-term, epilogue adds E)

#define BATCH 8
#define ENSN  256
#define XDIM  8192
#define NSQ   65536
#define SPLITS 8

__device__ __align__(256) float g_part[SPLITS * BATCH * NSQ];
__device__ __align__(256) float g_G[BATCH * NSQ];
__device__ __align__(256) float g_mu[BATCH * 256];
__device__ __align__(256) float g_A[BATCH * NSQ];
__device__ __align__(256) float g_Z[BATCH * NSQ];
__device__ __align__(256) float g_Dinv[BATCH * 8 * 32 * 32];
__device__ __align__(256) __half g_Ehi[BATCH * ENSN * XDIM];
__device__ __align__(256) __half g_Elo[BATCH * ENSN * XDIM];
__device__ __align__(256) __half g_Hhi[XDIM * 256];
__device__ __align__(256) __half g_Hlo[XDIM * 256];
__device__ __align__(256) __half g_Whi[BATCH * NSQ];
__device__ __align__(256) __half g_Wlo[BATCH * NSQ];

// ---------------- smem layout (bytes) ----------------
// A: [buf][hl][128 rows][40 el] fp16, row stride 80B (16B-aligned for ldsm)
// B: [buf][hl][32 rows][136 el] fp16, row stride 272B
#define SM_A(buf, hl) ((buf) * 20480 + (hl) * 10240)
#define SM_B(buf, hl) (40960 + (buf) * 17408 + (hl) * 8704)
#define GSMEM (40960 + 34816)

// ---------------- low-level helpers ----------------
__device__ __forceinline__ uint32_t smem_u32(const void* p) {
    uint32_t a;
    asm("{ .reg .u64 t; cvta.to.shared.u64 t, %1; cvt.u32.u64 %0, t; }" : "=r"(a) : "l"(p));
    return a;
}
__device__ __forceinline__ void cpa16(uint32_t dst, const void* src) {
    asm volatile("cp.async.cg.shared.global [%0], [%1], 16;" :: "r"(dst), "l"(src));
}
__device__ __forceinline__ void ldsm4(uint32_t* r, uint32_t a) {
    asm volatile("ldmatrix.sync.aligned.m8n8.x4.shared.b16 {%0,%1,%2,%3}, [%4];"
                 : "=r"(r[0]), "=r"(r[1]), "=r"(r[2]), "=r"(r[3]) : "r"(a));
}
__device__ __forceinline__ void ldsm4t(uint32_t* r, uint32_t a) {
    asm volatile("ldmatrix.sync.aligned.m8n8.x4.trans.shared.b16 {%0,%1,%2,%3}, [%4];"
                 : "=r"(r[0]), "=r"(r[1]), "=r"(r[2]), "=r"(r[3]) : "r"(a));
}
__device__ __forceinline__ void mma16816(float* c, const uint32_t* a, const uint32_t* b) {
    asm volatile("mma.sync.aligned.m16n8k16.row.col.f32.f16.f16.f32 "
                 "{%0,%1,%2,%3},{%4,%5,%6,%7},{%8,%9},{%0,%1,%2,%3};"
                 : "+f"(c[0]), "+f"(c[1]), "+f"(c[2]), "+f"(c[3])
                 : "r"(a[0]), "r"(a[1]), "r"(a[2]), "r"(a[3]), "r"(b[0]), "r"(b[1]));
}

// ---------------- tile producers ----------------
__device__ __forceinline__ void issue_tiles(
    uint32_t sb, int buf,
    const __half* __restrict__ Ahi, const __half* __restrict__ Alo, size_t lda,
    const __half* __restrict__ Bhi, const __half* __restrict__ Blo, size_t ldb,
    int kbase, int tid)
{
#pragma unroll
    for (int half_ = 0; half_ < 2; half_++) {
        const __half* src = half_ ? Alo : Ahi;
#pragma unroll
        for (int it = 0; it < 2; it++) {           // A: 512 16B chunks per half
            const int i = tid + it * 256;
            const int r = i >> 2, seg = i & 3;
            cpa16(sb + SM_A(buf, half_) + r * 80 + seg * 16,
                  src + (size_t)r * lda + kbase + seg * 8);
        }
    }
#pragma unroll
    for (int half_ = 0; half_ < 2; half_++) {
        const __half* src = half_ ? Blo : Bhi;
#pragma unroll
        for (int it = 0; it < 2; it++) {           // B: 512 16B chunks per half
            const int i = tid + it * 256;
            const int r = i >> 4, seg = i & 15;
            cpa16(sb + SM_B(buf, half_) + r * 272 + seg * 16,
                  src + (size_t)(kbase + r) * ldb + seg * 8);
        }
    }
}

// ---------------- warp compute: one 32-K chunk, 3-term fp16 split ----------------
// Register-lean: B frags resident per k16 (16 regs), A streamed per mi (8 regs).
__device__ __forceinline__ void compute_chunk(uint32_t sb, int buf, int lane,
                                              int wm, int wn, float acc[4][4][4]) {
    const int arow = lane & 15, aoff = (lane >> 4) * 16;
    const int brow = (lane & 7) + ((lane >> 3) & 1) * 8, boff = (lane >> 4) * 16;
#pragma unroll
    for (int k16 = 0; k16 < 2; k16++) {
        uint32_t bh[2][4], bl[2][4];
#pragma unroll
        for (int nj = 0; nj < 2; nj++) {
            ldsm4t(bh[nj], sb + SM_B(buf, 0) + (k16 * 16 + brow) * 272 + (wn + nj * 16) * 2 + boff);
            ldsm4t(bl[nj], sb + SM_B(buf, 1) + (k16 * 16 + brow) * 272 + (wn + nj * 16) * 2 + boff);
        }
#pragma unroll
        for (int mi = 0; mi < 4; mi++) {
            uint32_t ah[4], al[4];
            ldsm4(ah, sb + SM_A(buf, 0) + (wm + 16 * mi + arow) * 80 + k16 * 32 + aoff);
            ldsm4(al, sb + SM_A(buf, 1) + (wm + 16 * mi + arow) * 80 + k16 * 32 + aoff);
#pragma unroll
            for (int n8 = 0; n8 < 4; n8++) {
                mma16816(acc[mi][n8], ah, &bh[n8 >> 1][(n8 & 1) * 2]);
                mma16816(acc[mi][n8], ah, &bl[n8 >> 1][(n8 & 1) * 2]);
                mma16816(acc[mi][n8], al, &bh[n8 >> 1][(n8 & 1) * 2]);
            }
        }
    }
}

// ---------------- main accumulate driver (128m x 128n CTA) ----------------
__device__ __forceinline__ void mm_main(
    const __half* Ahi, const __half* Alo, size_t lda,
    const __half* Bhi, const __half* Blo, size_t ldb,
    int nch, float acc[4][4][4], char* smem)
{
    const uint32_t sb = smem_u32(smem);
    const int tid = threadIdx.x, lane = tid & 31, w = tid >> 5;
    const int wm = (w & 1) * 64, wn = (w >> 1) * 32;
#pragma unroll
    for (int i = 0; i < 4; i++)
#pragma unroll
        for (int j = 0; j < 4; j++)
#pragma unroll
            for (int q = 0; q < 4; q++) acc[i][j][q] = 0.0f;

    issue_tiles(sb, 0, Ahi, Alo, lda, Bhi, Blo, ldb, 0, tid);
    asm volatile("cp.async.commit_group;" ::: "memory");
    issue_tiles(sb, 1, Ahi, Alo, lda, Bhi, Blo, ldb, 32, tid);
    asm volatile("cp.async.commit_group;" ::: "memory");

    for (int c = 0; c < nch; c++) {
        asm volatile("cp.async.wait_group 1;" ::: "memory");
        __syncthreads();
        compute_chunk(sb, c & 1, lane, wm, wn, acc);
        __syncthreads();
        if (c + 2 < nch)
            issue_tiles(sb, c & 1, Ahi, Alo, lda, Bhi, Blo, ldb, (c + 2) * 32, tid);
        asm volatile("cp.async.commit_group;" ::: "memory");
    }
}

// ---------------------------------------------------------------------------
// GEMM1: split-K partials of G = E @ H.  grid(4 = mt*2+nt, 8 splits, 8 b)
// ---------------------------------------------------------------------------
__global__ __launch_bounds__(256, 2) void k_mm1() {
    extern __shared__ char smem[];
    const int mt = blockIdx.x >> 1, nt = blockIdx.x & 1;
    const int s = blockIdx.y, b = blockIdx.z;
    const size_t aoff = ((size_t)b * ENSN + mt * 128) * XDIM + (size_t)s * 1024;
    const size_t boff = (size_t)(s * 1024) * 256 + nt * 128;
    float acc[4][4][4];
    mm_main(g_Ehi + aoff, g_Elo + aoff, XDIM, g_Hhi + boff, g_Hlo + boff, 256, 32, acc, smem);

    float* Cp = g_part + (size_t)(s * BATCH + b) * NSQ + (mt * 128) * 256 + nt * 128;
    const int lane = threadIdx.x & 31, w = threadIdx.x >> 5;
    const int wm = (w & 1) * 64, wn = (w >> 1) * 32;
#pragma unroll
    for (int mi = 0; mi < 4; mi++)
#pragma unroll
        for (int n8 = 0; n8 < 4; n8++) {
            const int r = wm + 16 * mi + (lane >> 2);
            const int cc = wn + n8 * 8 + (lane & 3) * 2;
            *(float2*)(Cp + r * 256 + cc) = make_float2(acc[mi][n8][0], acc[mi][n8][1]);
            *(float2*)(Cp + (r + 8) * 256 + cc) = make_float2(acc[mi][n8][2], acc[mi][n8][3]);
        }
}

// ---------------------------------------------------------------------------
// GEMM3: out = E + Mt @ E.  grid(64 nt, 2 mt, 8 b)
// ---------------------------------------------------------------------------
__global__ __launch_bounds__(256, 2) void k_mm3(const float* __restrict__ E,
                                                float* __restrict__ out) {
    extern __shared__ char smem[];
    const int nt = blockIdx.x, mt = blockIdx.y, b = blockIdx.z;
    const int n0 = nt * 128;
    const size_t aoff = (size_t)b * NSQ + (size_t)(mt * 128) * 256;
    const size_t boff = (size_t)b * ENSN * XDIM + n0;
    float acc[4][4][4];
    mm_main(g_Whi + aoff, g_Wlo + aoff, 256, g_Ehi + boff, g_Elo + boff, XDIM, 8, acc, smem);

    const int lane = threadIdx.x & 31, w = threadIdx.x >> 5;
    const int wm = (w & 1) * 64, wn = (w >> 1) * 32;
    const float* Ep = E + (size_t)b * ENSN * XDIM;
    float* Op = out + (size_t)b * ENSN * XDIM;
#pragma unroll
    for (int mi = 0; mi < 4; mi++)
#pragma unroll
        for (int n8 = 0; n8 < 4; n8++) {
            const int e = mt * 128 + wm + 16 * mi + (lane >> 2);
            const int x = n0 + wn + n8 * 8 + (lane & 3) * 2;
            float2 e0 = *(const float2*)(Ep + (size_t)e * XDIM + x);
            float2 e1 = *(const float2*)(Ep + (size_t)(e + 8) * XDIM + x);
            *(float2*)(Op + (size_t)e * XDIM + x) =
                make_float2(e0.x + acc[mi][n8][0], e0.y + acc[mi][n8][1]);
            *(float2*)(Op + (size_t)(e + 8) * XDIM + x) =
                make_float2(e1.x + acc[mi][n8][2], e1.y + acc[mi][n8][3]);
        }
}

// ---------------------------------------------------------------------------
// fp16 hi/lo splits (elementwise)
// ---------------------------------------------------------------------------
__device__ __forceinline__ void split4h(float4 v, __half2* hi, __half2* lo, size_t idx2) {
    __half hx = __float2half_rn(v.x), hy = __float2half_rn(v.y);
    __half hz = __float2half_rn(v.z), hw = __float2half_rn(v.w);
    hi[idx2]     = __halves2half2(hx, hy);
    hi[idx2 + 1] = __halves2half2(hz, hw);
    lo[idx2]     = __halves2half2(__float2half_rn(v.x - __half2float(hx)),
                                  __float2half_rn(v.y - __half2float(hy)));
    lo[idx2 + 1] = __halves2half2(__float2half_rn(v.z - __half2float(hz)),
                                  __float2half_rn(v.w - __half2float(hw)));
}

__global__ __launch_bounds__(256) void k_splitE(const float* __restrict__ E) {
    const size_t i = (size_t)blockIdx.x * 256 + threadIdx.x;
    float4 v = ((const float4*)E)[i];
    split4h(v, (__half2*)g_Ehi, (__half2*)g_Elo, 2 * i);
}

__global__ __launch_bounds__(256) void k_splitH(const float* __restrict__ H) {
    const size_t i = (size_t)blockIdx.x * 256 + threadIdx.x;
    float4 v = ((const float4*)H)[i];
    split4h(v, (__half2*)g_Hhi, (__half2*)g_Hlo, 2 * i);
}

// ---------------------------------------------------------------------------
__global__ __launch_bounds__(256) void k_reduce() {
    const int i = blockIdx.x * 256 + threadIdx.x;
    const float4* P = (const float4*)g_part;
    float4 s = P[i];
#pragma unroll
    for (int p = 1; p < SPLITS; p++) {
        float4 v = P[(size_t)p * (BATCH * NSQ / 4) + i];
        s.x += v.x; s.y += v.y; s.z += v.z; s.w += v.w;
    }
    ((float4*)g_G)[i] = s;
}

__global__ __launch_bounds__(256) void k_colmean() {
    const int b = blockIdx.y;
    const int j = blockIdx.x * 32 + (threadIdx.x & 31);
    const int er = threadIdx.x >> 5;
    const float* G = g_G + b * NSQ;
    float s = 0.0f;
    for (int e = er; e < ENSN; e += 8) s += G[e * 256 + j];
    __shared__ float red[8][32];
    red[er][threadIdx.x & 31] = s;
    __syncthreads();
    if (er == 0) {
        float t = 0.0f;
#pragma unroll
        for (int r = 0; r < 8; r++) t += red[r][threadIdx.x & 31];
        g_mu[b * 256 + j] = t * (1.0f / 256.0f);
    }
}

__global__ __launch_bounds__(256) void k_centerT(const float* __restrict__ ymean,
                                                 const float* __restrict__ ystd,
                                                 const float* __restrict__ noise) {
    const int b = blockIdx.z, j0 = blockIdx.y * 32, e0 = blockIdx.x * 32;
    float* G = g_G + b * NSQ;
    float* Z = g_Z + b * NSQ;
    const float* nz = noise + b * NSQ;
    __shared__ float T[32][33];
    const int tx = threadIdx.x & 31, ty = threadIdx.x >> 5;
    const float mu = g_mu[b * 256 + j0 + tx];
#pragma unroll
    for (int r = 0; r < 4; r++) {
        const int e = e0 + ty + r * 8;
        float gc = G[e * 256 + j0 + tx] - mu;
        G[e * 256 + j0 + tx] = gc;
        T[ty + r * 8][tx] = gc;
    }
    __syncthreads();
#pragma unroll
    for (int r = 0; r < 4; r++) {
        const int j = j0 + ty + r * 8;
        const float ym = ymean[j];
        const float sd = ystd[j];
        Z[j * 256 + e0 + tx] = ym - T[tx][ty + r * 8] + nz[j * 256 + e0 + tx] * sd * sd;
    }
}

__global__ __launch_bounds__(256) void k_cyy(const float* __restrict__ ystd) {
    const int b = blockIdx.y;
    const int u0 = (blockIdx.x >> 2) * 64, v0 = (blockIdx.x & 3) * 64;
    const float* G = g_G + b * NSQ;
    float* A = g_A + b * NSQ;
    __shared__ float Us[16][64];
    __shared__ float Vs[16][64];
    const int tx = threadIdx.x & 15, ty = threadIdx.x >> 4;
    const int lk = threadIdx.x >> 4, lc = (threadIdx.x & 15) * 4;
    float acc[4][4];
#pragma unroll
    for (int i = 0; i < 4; i++)
#pragma unroll
        for (int j = 0; j < 4; j++) acc[i][j] = 0.0f;

    for (int ee = 0; ee < 256; ee += 16) {
        *(float4*)&Us[lk][lc] = *(const float4*)&G[(ee + lk) * 256 + u0 + lc];
        *(float4*)&Vs[lk][lc] = *(const float4*)&G[(ee + lk) * 256 + v0 + lc];
        __syncthreads();
#pragma unroll
        for (int k = 0; k < 16; k++) {
            float4 u = *(float4*)&Us[k][ty * 4];
            float4 v = *(float4*)&Vs[k][tx * 4];
            float ua[4] = {u.x, u.y, u.z, u.w};
            float va[4] = {v.x, v.y, v.z, v.w};
#pragma unroll
            for (int i = 0; i < 4; i++)
#pragma unroll
                for (int j = 0; j < 4; j++) acc[i][j] = fmaf(ua[i], va[j], acc[i][j]);
        }
        __syncthreads();
    }
#pragma unroll
    for (int i = 0; i < 4; i++)
#pragma unroll
        for (int j = 0; j < 4; j++) {
            const int u = u0 + ty * 4 + i, v = v0 + tx * 4 + j;
            float val = acc[i][j] * (1.0f / 256.0f);
            if (u == v) { float sd = ystd[u]; val += sd * sd; }
            A[u * 256 + v] = val;
        }
}

__global__ __launch_bounds__(256) void k_chol() {
    const int b = blockIdx.x;
    float* a = g_A + b * NSQ;
    __shared__ float P[256][33];
    __shared__ float sD[32];
    const int tid = threadIdx.x;

    for (int kb = 0; kb < 8; kb++) {
        const int j0 = kb * 32;
        if (tid >= j0) {
#pragma unroll
            for (int c = 0; c < 32; c++) P[tid][c] = a[tid * 256 + j0 + c];
        }
        __syncthreads();
        for (int k = 0; k < 32; k++) {
            const int gk = j0 + k;
            const float piv = P[gk][k];
            const float d = sqrtf(piv);
            const float rd = 1.0f / d;
            if (tid == gk) sD[k] = d;
            if (tid > gk) P[tid][k] *= rd;
            __syncthreads();
            if (tid > gk) {
                const float lrk = P[tid][k];
#pragma unroll
                for (int c = k + 1; c < 32; c++) P[tid][c] -= lrk * P[j0 + c][k];
            }
            __syncthreads();
        }
        if (tid >= j0) {
#pragma unroll
            for (int c = 0; c < 32; c++) {
                float val = P[tid][c];
                if (tid - j0 == c) val = sD[c];
                a[tid * 256 + j0 + c] = val;
            }
        }
        __syncthreads();
        const int rem = 224 - j0;
        if (rem > 0) {
            for (int idx = tid; idx < rem * rem; idx += 256) {
                const int r = j0 + 32 + idx / rem;
                const int c = j0 + 32 + (idx - (idx / rem) * rem);
                float acc = a[r * 256 + c];
#pragma unroll
                for (int k = 0; k < 32; k++) acc -= P[r][k] * P[c][k];
                a[r * 256 + c] = acc;
            }
        }
        __syncthreads();
    }
}

__global__ void k_invdiag() {
    const int p = blockIdx.x & 7, b = blockIdx.x >> 3, j0 = p * 32;
    const float* a = g_A + b * NSQ;
    __shared__ float Ld[32][33];
    __shared__ float Xc[32][33];
    const int lane = threadIdx.x;
    for (int i = 0; i < 32; i++) Ld[i][lane] = a[(j0 + i) * 256 + j0 + lane];
    __syncwarp();
    for (int i = 0; i < 32; i++) {
        float s = (i == lane) ? 1.0f : 0.0f;
        for (int k = lane; k < i; k++) s -= Ld[i][k] * Xc[k][lane];
        Xc[i][lane] = (i >= lane) ? s / Ld[i][i] : 0.0f;
    }
    __syncwarp();
    for (int i = 0; i < 32; i++)
        g_Dinv[(b * 8 + p) * 1024 + i * 32 + lane] = Xc[i][lane];
}

#define TS_SMEM 129920
__global__ __launch_bounds__(256) void k_trisolve2() {
    extern __shared__ float sm[];
    float (*Zs)[65] = (float(*)[65])sm;
    float (*Dv)[33] = (float(*)[33])(sm + 256 * 65);
    float (*Lp)[33] = (float(*)[33])(sm + 256 * 65 + 256 * 33);
    const int b = blockIdx.y, e0 = blockIdx.x * 64;
    const float* L = g_A + b * NSQ;
    float* Z = g_Z + b * NSQ;
    const int tid = threadIdx.x, c = tid & 63, rg = tid >> 6;

    for (int idx = tid; idx < 256 * 64; idx += 256)
        Zs[idx >> 6][idx & 63] = Z[(idx >> 6) * 256 + e0 + (idx & 63)];
    for (int idx = tid; idx < 8 * 32 * 32; idx += 256)
        Dv[idx >> 5][idx & 31] = g_Dinv[b * 8192 + idx];
    __syncthreads();

    for (int p = 0; p < 8; p++) {
        const int j0 = p * 32, rem = 224 - j0;
        float w[8];
#pragma unroll
        for (int q = 0; q < 8; q++) {
            const int r = rg * 8 + q;
            float s = 0.0f;
#pragma unroll
            for (int k = 0; k < 32; k++) s = fmaf(Dv[p * 32 + r][k], Zs[j0 + k][c], s);
            w[q] = s;
        }
        for (int idx = tid; idx < rem * 32; idx += 256)
            Lp[idx >> 5][idx & 31] = L[(j0 + 32 + (idx >> 5)) * 256 + j0 + (idx & 31)];
        __syncthreads();
#pragma unroll
        for (int q = 0; q < 8; q++) Zs[j0 + rg * 8 + q][c] = w[q];
        __syncthreads();
        for (int rr = rg; rr < rem; rr += 4) {
            float acc = Zs[j0 + 32 + rr][c];
#pragma unroll
            for (int k = 0; k < 32; k++) acc = fmaf(-Lp[rr][k], Zs[j0 + k][c], acc);
            Zs[j0 + 32 + rr][c] = acc;
        }
        __syncthreads();
    }

    for (int p = 7; p >= 0; p--) {
        const int j0 = p * 32;
        float w[8];
#pragma unroll
        for (int q = 0; q < 8; q++) {
            const int k = rg * 8 + q;
            float s = 0.0f;
#pragma unroll
            for (int i = 0; i < 32; i++) s = fmaf(Dv[p * 32 + i][k], Zs[j0 + i][c], s);
            w[q] = s;
        }
        for (int idx = tid; idx < j0 * 32; idx += 256)
            Lp[idx >> 5][idx & 31] = L[(j0 + (idx & 31)) * 256 + (idx >> 5)];
        __syncthreads();
#pragma unroll
        for (int q = 0; q < 8; q++) Zs[j0 + rg * 8 + q][c] = w[q];
        __syncthreads();
        for (int t = rg; t < j0; t += 4) {
            float acc = Zs[t][c];
#pragma unroll
            for (int k = 0; k < 32; k++) acc = fmaf(-Lp[t][k], Zs[j0 + k][c], acc);
            Zs[t][c] = acc;
        }
        __syncthreads();
    }

    for (int idx = tid; idx < 256 * 64; idx += 256)
        Z[(idx >> 6) * 256 + e0 + (idx & 63)] = Zs[idx >> 6][idx & 63];
}

// Mt[e][f] = (1/ens) sum_j Z[j][e] * Gc[f][j]  -> fp16 hi/lo
__global__ __launch_bounds__(256) void k_wp() {
    const int b = blockIdx.y;
    const int e0 = (blockIdx.x >> 2) * 64, f0 = (blockIdx.x & 3) * 64;
    const float* G = g_G + b * NSQ;
    const float* Z = g_Z + b * NSQ;
    __shared__ float sZ[16][64];
    __shared__ float sG[16][64];
    const int tx = threadIdx.x & 15, ty = threadIdx.x >> 4;
    const int lk = threadIdx.x >> 4, lc = (threadIdx.x & 15) * 4;
    const int gn = threadIdx.x >> 2, gk = (threadIdx.x & 3) * 4;
    float acc[4][4];
#pragma unroll
    for (int i = 0; i < 4; i++)
#pragma unroll
        for (int j = 0; j < 4; j++) acc[i][j] = 0.0f;

    for (int jj = 0; jj < 256; jj += 16) {
        *(float4*)&sZ[lk][lc] = *(const float4*)&Z[(jj + lk) * 256 + e0 + lc];
        float4 gv = *(const float4*)&G[(f0 + gn) * 256 + jj + gk];
        sG[gk + 0][gn] = gv.x; sG[gk + 1][gn] = gv.y;
        sG[gk + 2][gn] = gv.z; sG[gk + 3][gn] = gv.w;
        __syncthreads();
#pragma unroll
        for (int k = 0; k < 16; k++) {
            float4 zv = *(float4*)&sZ[k][ty * 4];
            float4 gg = *(float4*)&sG[k][tx * 4];
            float za[4] = {zv.x, zv.y, zv.z, zv.w};
            float ga[4] = {gg.x, gg.y, gg.z, gg.w};
#pragma unroll
            for (int i = 0; i < 4; i++)
#pragma unroll
                for (int j = 0; j < 4; j++) acc[i][j] = fmaf(za[i], ga[j], acc[i][j]);
        }
        __syncthreads();
    }
#pragma unroll
    for (int i = 0; i < 4; i++)
#pragma unroll
        for (int j = 0; j < 4; j++) {
            const int e = e0 + ty * 4 + i, f = f0 + tx * 4 + j;
            float val = acc[i][j] * (1.0f / 256.0f);
            __half h = __float2half_rn(val);
            g_Whi[b * NSQ + e * 256 + f] = h;
            g_Wlo[b * NSQ + e * 256 + f] = __float2half_rn(val - __half2float(h));
        }
}

// ---------------------------------------------------------------------------
extern "C" void kernel_launch(void* const* d_in, const int* in_sizes, int n_in,
                              void* d_out, int out_size) {
    const float* E     = (const float*)d_in[0];
    const float* H     = (const float*)d_in[1];
    const float* ymean = (const float*)d_in[2];
    const float* ystd  = (const float*)d_in[3];
    const float* noise = (const float*)d_in[4];
    float* out = (float*)d_out;

    cudaFuncSetAttribute(k_mm1, cudaFuncAttributeMaxDynamicSharedMemorySize, GSMEM);
    cudaFuncSetAttribute(k_mm3, cudaFuncAttributeMaxDynamicSharedMemorySize, GSMEM);
    cudaFuncSetAttribute(k_trisolve2, cudaFuncAttributeMaxDynamicSharedMemorySize, TS_SMEM);

    k_splitH<<<2048, 256>>>(H);
    k_splitE<<<16384, 256>>>(E);
    k_mm1<<<dim3(4, SPLITS, BATCH), 256, GSMEM>>>();
    k_reduce<<<(BATCH * NSQ / 4) / 256, 256>>>();
    k_colmean<<<dim3(8, BATCH), 256>>>();
    k_centerT<<<dim3(8, 8, BATCH), 256>>>(ymean, ystd, noise);
    k_cyy<<<dim3(16, BATCH), 256>>>(ystd);
    k_chol<<<BATCH, 256>>>();
    k_invdiag<<<64, 32>>>();
    k_trisolve2<<<dim3(4, BATCH), 256, TS_SMEM>>>();
    k_wp<<<dim3(16, BATCH), 256>>>();
    k_mm3<<<dim3(64, 2, BATCH), 256, GSMEM>>>(E, out);
}

// round 10
// speedup vs baseline: 1.3390x; 1.0735x over previous
#include <cuda_runtime.h>
#include <cuda_fp16.h>
#include <cstdint>

// EnsKF step. fp16 3-term split mma GEMMs (r9 config) + reg-cached trisolve.
//   G  = E @ H          (mma.m16n8k16.f16, hh+hl+lh, split-K)
//   Gc = G - colmean;  A = Gc^T Gc/ens + diag(std^2);  L = chol(A)
//   Dinv = inv of L's 32x32 diag blocks;  Z = A^{-1} innov (smem trisolve)
//   Mt[e][f] = (1/ens) sum_j Z[j][e] Gc[f][j]  -> fp16 hi/lo
//   out = E + Mt @ E    (mma fp16 3-term, epilogue adds E)

#define BATCH 8
#define ENSN  256
#define XDIM  8192
#define NSQ   65536
#define SPLITS 8

__device__ __align__(256) float g_part[SPLITS * BATCH * NSQ];
__device__ __align__(256) float g_G[BATCH * NSQ];
__device__ __align__(256) float g_mu[BATCH * 256];
__device__ __align__(256) float g_A[BATCH * NSQ];
__device__ __align__(256) float g_Z[BATCH * NSQ];
__device__ __align__(256) float g_Dinv[BATCH * 8 * 32 * 32];
__device__ __align__(256) __half g_Ehi[BATCH * ENSN * XDIM];
__device__ __align__(256) __half g_Elo[BATCH * ENSN * XDIM];
__device__ __align__(256) __half g_Hhi[XDIM * 256];
__device__ __align__(256) __half g_Hlo[XDIM * 256];
__device__ __align__(256) __half g_Whi[BATCH * NSQ];
__device__ __align__(256) __half g_Wlo[BATCH * NSQ];

// ---------------- smem layout (bytes) ----------------
#define SM_A(buf, hl) ((buf) * 20480 + (hl) * 10240)
#define SM_B(buf, hl) (40960 + (buf) * 17408 + (hl) * 8704)
#define GSMEM (40960 + 34816)

// ---------------- low-level helpers ----------------
__device__ __forceinline__ uint32_t smem_u32(const void* p) {
    uint32_t a;
    asm("{ .reg .u64 t; cvta.to.shared.u64 t, %1; cvt.u32.u64 %0, t; }" : "=r"(a) : "l"(p));
    return a;
}
__device__ __forceinline__ void cpa16(uint32_t dst, const void* src) {
    asm volatile("cp.async.cg.shared.global [%0], [%1], 16;" :: "r"(dst), "l"(src));
}
__device__ __forceinline__ void ldsm4(uint32_t* r, uint32_t a) {
    asm volatile("ldmatrix.sync.aligned.m8n8.x4.shared.b16 {%0,%1,%2,%3}, [%4];"
                 : "=r"(r[0]), "=r"(r[1]), "=r"(r[2]), "=r"(r[3]) : "r"(a));
}
__device__ __forceinline__ void ldsm4t(uint32_t* r, uint32_t a) {
    asm volatile("ldmatrix.sync.aligned.m8n8.x4.trans.shared.b16 {%0,%1,%2,%3}, [%4];"
                 : "=r"(r[0]), "=r"(r[1]), "=r"(r[2]), "=r"(r[3]) : "r"(a));
}
__device__ __forceinline__ void mma16816(float* c, const uint32_t* a, const uint32_t* b) {
    asm volatile("mma.sync.aligned.m16n8k16.row.col.f32.f16.f16.f32 "
                 "{%0,%1,%2,%3},{%4,%5,%6,%7},{%8,%9},{%0,%1,%2,%3};"
                 : "+f"(c[0]), "+f"(c[1]), "+f"(c[2]), "+f"(c[3])
                 : "r"(a[0]), "r"(a[1]), "r"(a[2]), "r"(a[3]), "r"(b[0]), "r"(b[1]));
}

// ---------------- tile producers ----------------
__device__ __forceinline__ void issue_tiles(
    uint32_t sb, int buf,
    const __half* __restrict__ Ahi, const __half* __restrict__ Alo, size_t lda,
    const __half* __restrict__ Bhi, const __half* __restrict__ Blo, size_t ldb,
    int kbase, int tid)
{
#pragma unroll
    for (int half_ = 0; half_ < 2; half_++) {
        const __half* src = half_ ? Alo : Ahi;
#pragma unroll
        for (int it = 0; it < 2; it++) {
            const int i = tid + it * 256;
            const int r = i >> 2, seg = i & 3;
            cpa16(sb + SM_A(buf, half_) + r * 80 + seg * 16,
                  src + (size_t)r * lda + kbase + seg * 8);
        }
    }
#pragma unroll
    for (int half_ = 0; half_ < 2; half_++) {
        const __half* src = half_ ? Blo : Bhi;
#pragma unroll
        for (int it = 0; it < 2; it++) {
            const int i = tid + it * 256;
            const int r = i >> 4, seg = i & 15;
            cpa16(sb + SM_B(buf, half_) + r * 272 + seg * 16,
                  src + (size_t)(kbase + r) * ldb + seg * 8);
        }
    }
}

// ---------------- warp compute: one 32-K chunk, 3-term fp16 split ----------------
__device__ __forceinline__ void compute_chunk(uint32_t sb, int buf, int lane,
                                              int wm, int wn, float acc[4][4][4]) {
    const int arow = lane & 15, aoff = (lane >> 4) * 16;
    const int brow = (lane & 7) + ((lane >> 3) & 1) * 8, boff = (lane >> 4) * 16;
#pragma unroll
    for (int k16 = 0; k16 < 2; k16++) {
        uint32_t bh[2][4], bl[2][4];
#pragma unroll
        for (int nj = 0; nj < 2; nj++) {
            ldsm4t(bh[nj], sb + SM_B(buf, 0) + (k16 * 16 + brow) * 272 + (wn + nj * 16) * 2 + boff);
            ldsm4t(bl[nj], sb + SM_B(buf, 1) + (k16 * 16 + brow) * 272 + (wn + nj * 16) * 2 + boff);
        }
#pragma unroll
        for (int mi = 0; mi < 4; mi++) {
            uint32_t ah[4], al[4];
            ldsm4(ah, sb + SM_A(buf, 0) + (wm + 16 * mi + arow) * 80 + k16 * 32 + aoff);
            ldsm4(al, sb + SM_A(buf, 1) + (wm + 16 * mi + arow) * 80 + k16 * 32 + aoff);
#pragma unroll
            for (int n8 = 0; n8 < 4; n8++) {
                mma16816(acc[mi][n8], ah, &bh[n8 >> 1][(n8 & 1) * 2]);
                mma16816(acc[mi][n8], ah, &bl[n8 >> 1][(n8 & 1) * 2]);
                mma16816(acc[mi][n8], al, &bh[n8 >> 1][(n8 & 1) * 2]);
            }
        }
    }
}

// ---------------- main accumulate driver (128m x 128n CTA) ----------------
__device__ __forceinline__ void mm_main(
    const __half* Ahi, const __half* Alo, size_t lda,
    const __half* Bhi, const __half* Blo, size_t ldb,
    int nch, float acc[4][4][4], char* smem)
{
    const uint32_t sb = smem_u32(smem);
    const int tid = threadIdx.x, lane = tid & 31, w = tid >> 5;
    const int wm = (w & 1) * 64, wn = (w >> 1) * 32;
#pragma unroll
    for (int i = 0; i < 4; i++)
#pragma unroll
        for (int j = 0; j < 4; j++)
#pragma unroll
            for (int q = 0; q < 4; q++) acc[i][j][q] = 0.0f;

    issue_tiles(sb, 0, Ahi, Alo, lda, Bhi, Blo, ldb, 0, tid);
    asm volatile("cp.async.commit_group;" ::: "memory");
    issue_tiles(sb, 1, Ahi, Alo, lda, Bhi, Blo, ldb, 32, tid);
    asm volatile("cp.async.commit_group;" ::: "memory");

    for (int c = 0; c < nch; c++) {
        asm volatile("cp.async.wait_group 1;" ::: "memory");
        __syncthreads();
        compute_chunk(sb, c & 1, lane, wm, wn, acc);
        __syncthreads();
        if (c + 2 < nch)
            issue_tiles(sb, c & 1, Ahi, Alo, lda, Bhi, Blo, ldb, (c + 2) * 32, tid);
        asm volatile("cp.async.commit_group;" ::: "memory");
    }
}

// ---------------------------------------------------------------------------
// GEMM1: split-K partials of G = E @ H.  grid(4 = mt*2+nt, 8 splits, 8 b)
// ---------------------------------------------------------------------------
__global__ __launch_bounds__(256, 2) void k_mm1() {
    extern __shared__ char smem[];
    const int mt = blockIdx.x >> 1, nt = blockIdx.x & 1;
    const int s = blockIdx.y, b = blockIdx.z;
    const size_t aoff = ((size_t)b * ENSN + mt * 128) * XDIM + (size_t)s * 1024;
    const size_t boff = (size_t)(s * 1024) * 256 + nt * 128;
    float acc[4][4][4];
    mm_main(g_Ehi + aoff, g_Elo + aoff, XDIM, g_Hhi + boff, g_Hlo + boff, 256, 32, acc, smem);

    float* Cp = g_part + (size_t)(s * BATCH + b) * NSQ + (mt * 128) * 256 + nt * 128;
    const int lane = threadIdx.x & 31, w = threadIdx.x >> 5;
    const int wm = (w & 1) * 64, wn = (w >> 1) * 32;
#pragma unroll
    for (int mi = 0; mi < 4; mi++)
#pragma unroll
        for (int n8 = 0; n8 < 4; n8++) {
            const int r = wm + 16 * mi + (lane >> 2);
            const int cc = wn + n8 * 8 + (lane & 3) * 2;
            *(float2*)(Cp + r * 256 + cc) = make_float2(acc[mi][n8][0], acc[mi][n8][1]);
            *(float2*)(Cp + (r + 8) * 256 + cc) = make_float2(acc[mi][n8][2], acc[mi][n8][3]);
        }
}

// ---------------------------------------------------------------------------
// GEMM3: out = E + Mt @ E.  grid(64 nt, 2 mt, 8 b)
// ---------------------------------------------------------------------------
__global__ __launch_bounds__(256, 2) void k_mm3(const float* __restrict__ E,
                                                float* __restrict__ out) {
    extern __shared__ char smem[];
    const int nt = blockIdx.x, mt = blockIdx.y, b = blockIdx.z;
    const int n0 = nt * 128;
    const size_t aoff = (size_t)b * NSQ + (size_t)(mt * 128) * 256;
    const size_t boff = (size_t)b * ENSN * XDIM + n0;
    float acc[4][4][4];
    mm_main(g_Whi + aoff, g_Wlo + aoff, 256, g_Ehi + boff, g_Elo + boff, XDIM, 8, acc, smem);

    const int lane = threadIdx.x & 31, w = threadIdx.x >> 5;
    const int wm = (w & 1) * 64, wn = (w >> 1) * 32;
    const float* Ep = E + (size_t)b * ENSN * XDIM;
    float* Op = out + (size_t)b * ENSN * XDIM;
#pragma unroll
    for (int mi = 0; mi < 4; mi++)
#pragma unroll
        for (int n8 = 0; n8 < 4; n8++) {
            const int e = mt * 128 + wm + 16 * mi + (lane >> 2);
            const int x = n0 + wn + n8 * 8 + (lane & 3) * 2;
            float2 e0 = *(const float2*)(Ep + (size_t)e * XDIM + x);
            float2 e1 = *(const float2*)(Ep + (size_t)(e + 8) * XDIM + x);
            *(float2*)(Op + (size_t)e * XDIM + x) =
                make_float2(e0.x + acc[mi][n8][0], e0.y + acc[mi][n8][1]);
            *(float2*)(Op + (size_t)(e + 8) * XDIM + x) =
                make_float2(e1.x + acc[mi][n8][2], e1.y + acc[mi][n8][3]);
        }
}

// ---------------------------------------------------------------------------
// Dummy at launch index 0 so ncu (captures index 3) profiles k_mm1.
// Writes g_mu (fully overwritten by k_colmean later) — deterministic, harmless.
// ---------------------------------------------------------------------------
__global__ void k_dummy() {
    const int i = threadIdx.x;
#pragma unroll
    for (int r = 0; r < 8; r++) g_mu[r * 256 + i] = 0.0f;
}

// ---------------------------------------------------------------------------
// fp16 hi/lo splits (elementwise)
// ---------------------------------------------------------------------------
__device__ __forceinline__ void split4h(float4 v, __half2* hi, __half2* lo, size_t idx2) {
    __half hx = __float2half_rn(v.x), hy = __float2half_rn(v.y);
    __half hz = __float2half_rn(v.z), hw = __float2half_rn(v.w);
    hi[idx2]     = __halves2half2(hx, hy);
    hi[idx2 + 1] = __halves2half2(hz, hw);
    lo[idx2]     = __halves2half2(__float2half_rn(v.x - __half2float(hx)),
                                  __float2half_rn(v.y - __half2float(hy)));
    lo[idx2 + 1] = __halves2half2(__float2half_rn(v.z - __half2float(hz)),
                                  __float2half_rn(v.w - __half2float(hw)));
}

__global__ __launch_bounds__(256) void k_splitE(const float* __restrict__ E) {
    const size_t i = (size_t)blockIdx.x * 256 + threadIdx.x;
    float4 v = ((const float4*)E)[i];
    split4h(v, (__half2*)g_Ehi, (__half2*)g_Elo, 2 * i);
}

__global__ __launch_bounds__(256) void k_splitH(const float* __restrict__ H) {
    const size_t i = (size_t)blockIdx.x * 256 + threadIdx.x;
    float4 v = ((const float4*)H)[i];
    split4h(v, (__half2*)g_Hhi, (__half2*)g_Hlo, 2 * i);
}

// ---------------------------------------------------------------------------
__global__ __launch_bounds__(256) void k_reduce() {
    const int i = blockIdx.x * 256 + threadIdx.x;
    const float4* P = (const float4*)g_part;
    float4 s = P[i];
#pragma unroll
    for (int p = 1; p < SPLITS; p++) {
        float4 v = P[(size_t)p * (BATCH * NSQ / 4) + i];
        s.x += v.x; s.y += v.y; s.z += v.z; s.w += v.w;
    }
    ((float4*)g_G)[i] = s;
}

__global__ __launch_bounds__(256) void k_colmean() {
    const int b = blockIdx.y;
    const int j = blockIdx.x * 32 + (threadIdx.x & 31);
    const int er = threadIdx.x >> 5;
    const float* G = g_G + b * NSQ;
    float s = 0.0f;
    for (int e = er; e < ENSN; e += 8) s += G[e * 256 + j];
    __shared__ float red[8][32];
    red[er][threadIdx.x & 31] = s;
    __syncthreads();
    if (er == 0) {
        float t = 0.0f;
#pragma unroll
        for (int r = 0; r < 8; r++) t += red[r][threadIdx.x & 31];
        g_mu[b * 256 + j] = t * (1.0f / 256.0f);
    }
}

__global__ __launch_bounds__(256) void k_centerT(const float* __restrict__ ymean,
                                                 const float* __restrict__ ystd,
                                                 const float* __restrict__ noise) {
    const int b = blockIdx.z, j0 = blockIdx.y * 32, e0 = blockIdx.x * 32;
    float* G = g_G + b * NSQ;
    float* Z = g_Z + b * NSQ;
    const float* nz = noise + b * NSQ;
    __shared__ float T[32][33];
    const int tx = threadIdx.x & 31, ty = threadIdx.x >> 5;
    const float mu = g_mu[b * 256 + j0 + tx];
#pragma unroll
    for (int r = 0; r < 4; r++) {
        const int e = e0 + ty + r * 8;
        float gc = G[e * 256 + j0 + tx] - mu;
        G[e * 256 + j0 + tx] = gc;
        T[ty + r * 8][tx] = gc;
    }
    __syncthreads();
#pragma unroll
    for (int r = 0; r < 4; r++) {
        const int j = j0 + ty + r * 8;
        const float ym = ymean[j];
        const float sd = ystd[j];
        Z[j * 256 + e0 + tx] = ym - T[tx][ty + r * 8] + nz[j * 256 + e0 + tx] * sd * sd;
    }
}

__global__ __launch_bounds__(256) void k_cyy(const float* __restrict__ ystd) {
    const int b = blockIdx.y;
    const int u0 = (blockIdx.x >> 2) * 64, v0 = (blockIdx.x & 3) * 64;
    const float* G = g_G + b * NSQ;
    float* A = g_A + b * NSQ;
    __shared__ float Us[16][64];
    __shared__ float Vs[16][64];
    const int tx = threadIdx.x & 15, ty = threadIdx.x >> 4;
    const int lk = threadIdx.x >> 4, lc = (threadIdx.x & 15) * 4;
    float acc[4][4];
#pragma unroll
    for (int i = 0; i < 4; i++)
#pragma unroll
        for (int j = 0; j < 4; j++) acc[i][j] = 0.0f;

    for (int ee = 0; ee < 256; ee += 16) {
        *(float4*)&Us[lk][lc] = *(const float4*)&G[(ee + lk) * 256 + u0 + lc];
        *(float4*)&Vs[lk][lc] = *(const float4*)&G[(ee + lk) * 256 + v0 + lc];
        __syncthreads();
#pragma unroll
        for (int k = 0; k < 16; k++) {
            float4 u = *(float4*)&Us[k][ty * 4];
            float4 v = *(float4*)&Vs[k][tx * 4];
            float ua[4] = {u.x, u.y, u.z, u.w};
            float va[4] = {v.x, v.y, v.z, v.w};
#pragma unroll
            for (int i = 0; i < 4; i++)
#pragma unroll
                for (int j = 0; j < 4; j++) acc[i][j] = fmaf(ua[i], va[j], acc[i][j]);
        }
        __syncthreads();
    }
#pragma unroll
    for (int i = 0; i < 4; i++)
#pragma unroll
        for (int j = 0; j < 4; j++) {
            const int u = u0 + ty * 4 + i, v = v0 + tx * 4 + j;
            float val = acc[i][j] * (1.0f / 256.0f);
            if (u == v) { float sd = ystd[u]; val += sd * sd; }
            A[u * 256 + v] = val;
        }
}

__global__ __launch_bounds__(256) void k_chol() {
    const int b = blockIdx.x;
    float* a = g_A + b * NSQ;
    __shared__ float P[256][33];
    __shared__ float sD[32];
    const int tid = threadIdx.x;

    for (int kb = 0; kb < 8; kb++) {
        const int j0 = kb * 32;
        if (tid >= j0) {
#pragma unroll
            for (int c = 0; c < 32; c++) P[tid][c] = a[tid * 256 + j0 + c];
        }
        __syncthreads();
        for (int k = 0; k < 32; k++) {
            const int gk = j0 + k;
            const float piv = P[gk][k];
            const float d = sqrtf(piv);
            const float rd = 1.0f / d;
            if (tid == gk) sD[k] = d;
            if (tid > gk) P[tid][k] *= rd;
            __syncthreads();
            if (tid > gk) {
                const float lrk = P[tid][k];
#pragma unroll
                for (int c = k + 1; c < 32; c++) P[tid][c] -= lrk * P[j0 + c][k];
            }
            __syncthreads();
        }
        if (tid >= j0) {
#pragma unroll
            for (int c = 0; c < 32; c++) {
                float val = P[tid][c];
                if (tid - j0 == c) val = sD[c];
                a[tid * 256 + j0 + c] = val;
            }
        }
        __syncthreads();
        const int rem = 224 - j0;
        if (rem > 0) {
            for (int idx = tid; idx < rem * rem; idx += 256) {
                const int r = j0 + 32 + idx / rem;
                const int c = j0 + 32 + (idx - (idx / rem) * rem);
                float acc = a[r * 256 + c];
#pragma unroll
                for (int k = 0; k < 32; k++) acc -= P[r][k] * P[c][k];
                a[r * 256 + c] = acc;
            }
        }
        __syncthreads();
    }
}

__global__ void k_invdiag() {
    const int p = blockIdx.x & 7, b = blockIdx.x >> 3, j0 = p * 32;
    const float* a = g_A + b * NSQ;
    __shared__ float Ld[32][33];
    __shared__ float Xc[32][33];
    const int lane = threadIdx.x;
    for (int i = 0; i < 32; i++) Ld[i][lane] = a[(j0 + i) * 256 + j0 + lane];
    __syncwarp();
    for (int i = 0; i < 32; i++) {
        float s = (i == lane) ? 1.0f : 0.0f;
        for (int k = lane; k < i; k++) s -= Ld[i][k] * Xc[k][lane];
        Xc[i][lane] = (i >= lane) ? s / Ld[i][i] : 0.0f;
    }
    __syncwarp();
    for (int i = 0; i < 32; i++)
        g_Dinv[(b * 8 + p) * 1024 + i * 32 + lane] = Xc[i][lane];
}

// ---------------------------------------------------------------------------
// Trisolve, register-cached Z panel (1 LDS-broadcast + 1 FMA inner loop)
// ---------------------------------------------------------------------------
#define TS_SMEM 129920
__global__ __launch_bounds__(256) void k_trisolve2() {
    extern __shared__ float sm[];
    float (*Zs)[65] = (float(*)[65])sm;
    float (*Dv)[33] = (float(*)[33])(sm + 256 * 65);
    float (*Lp)[33] = (float(*)[33])(sm + 256 * 65 + 256 * 33);
    const int b = blockIdx.y, e0 = blockIdx.x * 64;
    const float* L = g_A + b * NSQ;
    float* Z = g_Z + b * NSQ;
    const int tid = threadIdx.x, c = tid & 63, rg = tid >> 6;

    for (int idx = tid; idx < 256 * 64; idx += 256)
        Zs[idx >> 6][idx & 63] = Z[(idx >> 6) * 256 + e0 + (idx & 63)];
    for (int idx = tid; idx < 8 * 32 * 32; idx += 256)
        Dv[idx >> 5][idx & 31] = g_Dinv[b * 8192 + idx];
    __syncthreads();

    // forward: L y = innov
    for (int p = 0; p < 8; p++) {
        const int j0 = p * 32, rem = 224 - j0;
        float zr[32];
#pragma unroll
        for (int k = 0; k < 32; k++) zr[k] = Zs[j0 + k][c];
        float w[8];
#pragma unroll
        for (int q = 0; q < 8; q++) {
            const int r = rg * 8 + q;
            float s = 0.0f;
#pragma unroll
            for (int k = 0; k < 32; k++) s = fmaf(Dv[p * 32 + r][k], zr[k], s);
            w[q] = s;
        }
        for (int idx = tid; idx < rem * 32; idx += 256)
            Lp[idx >> 5][idx & 31] = L[(j0 + 32 + (idx >> 5)) * 256 + j0 + (idx & 31)];
        __syncthreads();
#pragma unroll
        for (int q = 0; q < 8; q++) Zs[j0 + rg * 8 + q][c] = w[q];
        __syncthreads();
#pragma unroll
        for (int k = 0; k < 32; k++) zr[k] = Zs[j0 + k][c];
        for (int rr = rg; rr < rem; rr += 4) {
            float acc = Zs[j0 + 32 + rr][c];
#pragma unroll
            for (int k = 0; k < 32; k++) acc = fmaf(-Lp[rr][k], zr[k], acc);
            Zs[j0 + 32 + rr][c] = acc;
        }
        __syncthreads();
    }

    // backward: L^T z = y
    for (int p = 7; p >= 0; p--) {
        const int j0 = p * 32;
        float zr[32];
#pragma unroll
        for (int i = 0; i < 32; i++) zr[i] = Zs[j0 + i][c];
        float w[8];
#pragma unroll
        for (int q = 0; q < 8; q++) {
            const int k = rg * 8 + q;
            float s = 0.0f;
#pragma unroll
            for (int i = 0; i < 32; i++) s = fmaf(Dv[p * 32 + i][k], zr[i], s);
            w[q] = s;
        }
        for (int idx = tid; idx < j0 * 32; idx += 256)
            Lp[idx >> 5][idx & 31] = L[(j0 + (idx & 31)) * 256 + (idx >> 5)];
        __syncthreads();
#pragma unroll
        for (int q = 0; q < 8; q++) Zs[j0 + rg * 8 + q][c] = w[q];
        __syncthreads();
#pragma unroll
        for (int k = 0; k < 32; k++) zr[k] = Zs[j0 + k][c];
        for (int t = rg; t < j0; t += 4) {
            float acc = Zs[t][c];
#pragma unroll
            for (int k = 0; k < 32; k++) acc = fmaf(-Lp[t][k], zr[k], acc);
            Zs[t][c] = acc;
        }
        __syncthreads();
    }

    for (int idx = tid; idx < 256 * 64; idx += 256)
        Z[(idx >> 6) * 256 + e0 + (idx & 63)] = Zs[idx >> 6][idx & 63];
}

// Mt[e][f] = (1/ens) sum_j Z[j][e] * Gc[f][j]  -> fp16 hi/lo
__global__ __launch_bounds__(256) void k_wp() {
    const int b = blockIdx.y;
    const int e0 = (blockIdx.x >> 2) * 64, f0 = (blockIdx.x & 3) * 64;
    const float* G = g_G + b * NSQ;
    const float* Z = g_Z + b * NSQ;
    __shared__ float sZ[16][64];
    __shared__ float sG[16][64];
    const int tx = threadIdx.x & 15, ty = threadIdx.x >> 4;
    const int lk = threadIdx.x >> 4, lc = (threadIdx.x & 15) * 4;
    const int gn = threadIdx.x >> 2, gk = (threadIdx.x & 3) * 4;
    float acc[4][4];
#pragma unroll
    for (int i = 0; i < 4; i++)
#pragma unroll
        for (int j = 0; j < 4; j++) acc[i][j] = 0.0f;

    for (int jj = 0; jj < 256; jj += 16) {
        *(float4*)&sZ[lk][lc] = *(const float4*)&Z[(jj + lk) * 256 + e0 + lc];
        float4 gv = *(const float4*)&G[(f0 + gn) * 256 + jj + gk];
        sG[gk + 0][gn] = gv.x; sG[gk + 1][gn] = gv.y;
        sG[gk + 2][gn] = gv.z; sG[gk + 3][gn] = gv.w;
        __syncthreads();
#pragma unroll
        for (int k = 0; k < 16; k++) {
            float4 zv = *(float4*)&sZ[k][ty * 4];
            float4 gg = *(float4*)&sG[k][tx * 4];
            float za[4] = {zv.x, zv.y, zv.z, zv.w};
            float ga[4] = {gg.x, gg.y, gg.z, gg.w};
#pragma unroll
            for (int i = 0; i < 4; i++)
#pragma unroll
                for (int j = 0; j < 4; j++) acc[i][j] = fmaf(za[i], ga[j], acc[i][j]);
        }
        __syncthreads();
    }
#pragma unroll
    for (int i = 0; i < 4; i++)
#pragma unroll
        for (int j = 0; j < 4; j++) {
            const int e = e0 + ty * 4 + i, f = f0 + tx * 4 + j;
            float val = acc[i][j] * (1.0f / 256.0f);
            __half h = __float2half_rn(val);
            g_Whi[b * NSQ + e * 256 + f] = h;
            g_Wlo[b * NSQ + e * 256 + f] = __float2half_rn(val - __half2float(h));
        }
}

// ---------------------------------------------------------------------------
extern "C" void kernel_launch(void* const* d_in, const int* in_sizes, int n_in,
                              void* d_out, int out_size) {
    const float* E     = (const float*)d_in[0];
    const float* H     = (const float*)d_in[1];
    const float* ymean = (const float*)d_in[2];
    const float* ystd  = (const float*)d_in[3];
    const float* noise = (const float*)d_in[4];
    float* out = (float*)d_out;

    cudaFuncSetAttribute(k_mm1, cudaFuncAttributeMaxDynamicSharedMemorySize, GSMEM);
    cudaFuncSetAttribute(k_mm3, cudaFuncAttributeMaxDynamicSharedMemorySize, GSMEM);
    cudaFuncSetAttribute(k_trisolve2, cudaFuncAttributeMaxDynamicSharedMemorySize, TS_SMEM);

    k_dummy<<<1, 256>>>();                                  // idx 0 (shifts mm1 to idx 3)
    k_splitH<<<2048, 256>>>(H);                             // idx 1
    k_splitE<<<16384, 256>>>(E);                            // idx 2
    k_mm1<<<dim3(4, SPLITS, BATCH), 256, GSMEM>>>();        // idx 3  <- ncu capture
    k_reduce<<<(BATCH * NSQ / 4) / 256, 256>>>();
    k_colmean<<<dim3(8, BATCH), 256>>>();
    k_centerT<<<dim3(8, 8, BATCH), 256>>>(ymean, ystd, noise);
    k_cyy<<<dim3(16, BATCH), 256>>>(ystd);
    k_chol<<<BATCH, 256>>>();
    k_invdiag<<<64, 32>>>();
    k_trisolve2<<<dim3(4, BATCH), 256, TS_SMEM>>>();
    k_wp<<<dim3(16, BATCH), 256>>>();
    k_mm3<<<dim3(64, 2, BATCH), 256, GSMEM>>>(E, out);
}

// round 11
// speedup vs baseline: 1.7946x; 1.3402x over previous
#include <cuda_runtime.h>
#include <cuda_fp16.h>
#include <cstdint>

// EnsKF step. fp16 3-term split mma GEMMs + reg-blocked chol + reg-cached trisolve.
//   G  = E @ H          (mma.m16n8k16.f16, hh+hl+lh, split-K)
//   Gc = G - colmean;  A = Gc^T Gc/ens + diag(std^2);  L = chol(A)
//   Dinv = inv of L's 32x32 diag blocks;  Z = A^{-1} innov (smem trisolve)
//   W' = I + (1/ens)(Gc @ Z)^T  -> fp16 hi/lo
//   out = W' @ E        (mma fp16 3-term, store-only epilogue)

#define BATCH 8
#define ENSN  256
#define XDIM  8192
#define NSQ   65536
#define SPLITS 8

__device__ __align__(256) float g_part[SPLITS * BATCH * NSQ];
__device__ __align__(256) float g_G[BATCH * NSQ];
__device__ __align__(256) float g_mu[BATCH * 256];
__device__ __align__(256) float g_A[BATCH * NSQ];
__device__ __align__(256) float g_Z[BATCH * NSQ];
__device__ __align__(256) float g_Dinv[BATCH * 8 * 32 * 32];
__device__ __align__(256) __half g_Ehi[BATCH * ENSN * XDIM];
__device__ __align__(256) __half g_Elo[BATCH * ENSN * XDIM];
__device__ __align__(256) __half g_Hhi[XDIM * 256];
__device__ __align__(256) __half g_Hlo[XDIM * 256];
__device__ __align__(256) __half g_Whi[BATCH * NSQ];
__device__ __align__(256) __half g_Wlo[BATCH * NSQ];

// ---------------- smem layout (bytes) ----------------
#define SM_A(buf, hl) ((buf) * 20480 + (hl) * 10240)
#define SM_B(buf, hl) (40960 + (buf) * 17408 + (hl) * 8704)
#define GSMEM (40960 + 34816)

// ---------------- low-level helpers ----------------
__device__ __forceinline__ uint32_t smem_u32(const void* p) {
    uint32_t a;
    asm("{ .reg .u64 t; cvta.to.shared.u64 t, %1; cvt.u32.u64 %0, t; }" : "=r"(a) : "l"(p));
    return a;
}
__device__ __forceinline__ void cpa16(uint32_t dst, const void* src) {
    asm volatile("cp.async.cg.shared.global [%0], [%1], 16;" :: "r"(dst), "l"(src));
}
__device__ __forceinline__ void ldsm4(uint32_t* r, uint32_t a) {
    asm volatile("ldmatrix.sync.aligned.m8n8.x4.shared.b16 {%0,%1,%2,%3}, [%4];"
                 : "=r"(r[0]), "=r"(r[1]), "=r"(r[2]), "=r"(r[3]) : "r"(a));
}
__device__ __forceinline__ void ldsm4t(uint32_t* r, uint32_t a) {
    asm volatile("ldmatrix.sync.aligned.m8n8.x4.trans.shared.b16 {%0,%1,%2,%3}, [%4];"
                 : "=r"(r[0]), "=r"(r[1]), "=r"(r[2]), "=r"(r[3]) : "r"(a));
}
__device__ __forceinline__ void mma16816(float* c, const uint32_t* a, const uint32_t* b) {
    asm volatile("mma.sync.aligned.m16n8k16.row.col.f32.f16.f16.f32 "
                 "{%0,%1,%2,%3},{%4,%5,%6,%7},{%8,%9},{%0,%1,%2,%3};"
                 : "+f"(c[0]), "+f"(c[1]), "+f"(c[2]), "+f"(c[3])
                 : "r"(a[0]), "r"(a[1]), "r"(a[2]), "r"(a[3]), "r"(b[0]), "r"(b[1]));
}

// ---------------- tile producers ----------------
__device__ __forceinline__ void issue_tiles(
    uint32_t sb, int buf,
    const __half* __restrict__ Ahi, const __half* __restrict__ Alo, size_t lda,
    const __half* __restrict__ Bhi, const __half* __restrict__ Blo, size_t ldb,
    int kbase, int tid)
{
#pragma unroll
    for (int half_ = 0; half_ < 2; half_++) {
        const __half* src = half_ ? Alo : Ahi;
#pragma unroll
        for (int it = 0; it < 2; it++) {
            const int i = tid + it * 256;
            const int r = i >> 2, seg = i & 3;
            cpa16(sb + SM_A(buf, half_) + r * 80 + seg * 16,
                  src + (size_t)r * lda + kbase + seg * 8);
        }
    }
#pragma unroll
    for (int half_ = 0; half_ < 2; half_++) {
        const __half* src = half_ ? Blo : Bhi;
#pragma unroll
        for (int it = 0; it < 2; it++) {
            const int i = tid + it * 256;
            const int r = i >> 4, seg = i & 15;
            cpa16(sb + SM_B(buf, half_) + r * 272 + seg * 16,
                  src + (size_t)(kbase + r) * ldb + seg * 8);
        }
    }
}

// ---------------- warp compute: one 32-K chunk, 3-term fp16 split ----------------
__device__ __forceinline__ void compute_chunk(uint32_t sb, int buf, int lane,
                                              int wm, int wn, float acc[4][4][4]) {
    const int arow = lane & 15, aoff = (lane >> 4) * 16;
    const int brow = (lane & 7) + ((lane >> 3) & 1) * 8, boff = (lane >> 4) * 16;
#pragma unroll
    for (int k16 = 0; k16 < 2; k16++) {
        uint32_t bh[2][4], bl[2][4];
#pragma unroll
        for (int nj = 0; nj < 2; nj++) {
            ldsm4t(bh[nj], sb + SM_B(buf, 0) + (k16 * 16 + brow) * 272 + (wn + nj * 16) * 2 + boff);
            ldsm4t(bl[nj], sb + SM_B(buf, 1) + (k16 * 16 + brow) * 272 + (wn + nj * 16) * 2 + boff);
        }
#pragma unroll
        for (int mi = 0; mi < 4; mi++) {
            uint32_t ah[4], al[4];
            ldsm4(ah, sb + SM_A(buf, 0) + (wm + 16 * mi + arow) * 80 + k16 * 32 + aoff);
            ldsm4(al, sb + SM_A(buf, 1) + (wm + 16 * mi + arow) * 80 + k16 * 32 + aoff);
#pragma unroll
            for (int n8 = 0; n8 < 4; n8++) {
                mma16816(acc[mi][n8], ah, &bh[n8 >> 1][(n8 & 1) * 2]);
                mma16816(acc[mi][n8], ah, &bl[n8 >> 1][(n8 & 1) * 2]);
                mma16816(acc[mi][n8], al, &bh[n8 >> 1][(n8 & 1) * 2]);
            }
        }
    }
}

// ---------------- main accumulate driver (128m x 128n CTA) ----------------
__device__ __forceinline__ void mm_main(
    const __half* Ahi, const __half* Alo, size_t lda,
    const __half* Bhi, const __half* Blo, size_t ldb,
    int nch, float acc[4][4][4], char* smem)
{
    const uint32_t sb = smem_u32(smem);
    const int tid = threadIdx.x, lane = tid & 31, w = tid >> 5;
    const int wm = (w & 1) * 64, wn = (w >> 1) * 32;
#pragma unroll
    for (int i = 0; i < 4; i++)
#pragma unroll
        for (int j = 0; j < 4; j++)
#pragma unroll
            for (int q = 0; q < 4; q++) acc[i][j][q] = 0.0f;

    issue_tiles(sb, 0, Ahi, Alo, lda, Bhi, Blo, ldb, 0, tid);
    asm volatile("cp.async.commit_group;" ::: "memory");
    issue_tiles(sb, 1, Ahi, Alo, lda, Bhi, Blo, ldb, 32, tid);
    asm volatile("cp.async.commit_group;" ::: "memory");

    for (int c = 0; c < nch; c++) {
        asm volatile("cp.async.wait_group 1;" ::: "memory");
        __syncthreads();
        compute_chunk(sb, c & 1, lane, wm, wn, acc);
        __syncthreads();
        if (c + 2 < nch)
            issue_tiles(sb, c & 1, Ahi, Alo, lda, Bhi, Blo, ldb, (c + 2) * 32, tid);
        asm volatile("cp.async.commit_group;" ::: "memory");
    }
}

// ---------------------------------------------------------------------------
// GEMM1: split-K partials of G = E @ H.  grid(4 = mt*2+nt, 8 splits, 8 b)
// ---------------------------------------------------------------------------
__global__ __launch_bounds__(256, 2) void k_mm1() {
    extern __shared__ char smem[];
    const int mt = blockIdx.x >> 1, nt = blockIdx.x & 1;
    const int s = blockIdx.y, b = blockIdx.z;
    const size_t aoff = ((size_t)b * ENSN + mt * 128) * XDIM + (size_t)s * 1024;
    const size_t boff = (size_t)(s * 1024) * 256 + nt * 128;
    float acc[4][4][4];
    mm_main(g_Ehi + aoff, g_Elo + aoff, XDIM, g_Hhi + boff, g_Hlo + boff, 256, 32, acc, smem);

    float* Cp = g_part + (size_t)(s * BATCH + b) * NSQ + (mt * 128) * 256 + nt * 128;
    const int lane = threadIdx.x & 31, w = threadIdx.x >> 5;
    const int wm = (w & 1) * 64, wn = (w >> 1) * 32;
#pragma unroll
    for (int mi = 0; mi < 4; mi++)
#pragma unroll
        for (int n8 = 0; n8 < 4; n8++) {
            const int r = wm + 16 * mi + (lane >> 2);
            const int cc = wn + n8 * 8 + (lane & 3) * 2;
            *(float2*)(Cp + r * 256 + cc) = make_float2(acc[mi][n8][0], acc[mi][n8][1]);
            *(float2*)(Cp + (r + 8) * 256 + cc) = make_float2(acc[mi][n8][2], acc[mi][n8][3]);
        }
}

// ---------------------------------------------------------------------------
// GEMM3: out = W' @ E.  grid(64 nt, 2 mt, 8 b)  (identity folded into W')
// ---------------------------------------------------------------------------
__global__ __launch_bounds__(256, 2) void k_mm3(float* __restrict__ out) {
    extern __shared__ char smem[];
    const int nt = blockIdx.x, mt = blockIdx.y, b = blockIdx.z;
    const int n0 = nt * 128;
    const size_t aoff = (size_t)b * NSQ + (size_t)(mt * 128) * 256;
    const size_t boff = (size_t)b * ENSN * XDIM + n0;
    float acc[4][4][4];
    mm_main(g_Whi + aoff, g_Wlo + aoff, 256, g_Ehi + boff, g_Elo + boff, XDIM, 8, acc, smem);

    const int lane = threadIdx.x & 31, w = threadIdx.x >> 5;
    const int wm = (w & 1) * 64, wn = (w >> 1) * 32;
    float* Op = out + (size_t)b * ENSN * XDIM;
#pragma unroll
    for (int mi = 0; mi < 4; mi++)
#pragma unroll
        for (int n8 = 0; n8 < 4; n8++) {
            const int e = mt * 128 + wm + 16 * mi + (lane >> 2);
            const int x = n0 + wn + n8 * 8 + (lane & 3) * 2;
            *(float2*)(Op + (size_t)e * XDIM + x) =
                make_float2(acc[mi][n8][0], acc[mi][n8][1]);
            *(float2*)(Op + (size_t)(e + 8) * XDIM + x) =
                make_float2(acc[mi][n8][2], acc[mi][n8][3]);
        }
}

// ---------------------------------------------------------------------------
// Dummy at launch index 0 so ncu (captures index 3) profiles k_mm1.
// ---------------------------------------------------------------------------
__global__ void k_dummy() {
    const int i = threadIdx.x;
#pragma unroll
    for (int r = 0; r < 8; r++) g_mu[r * 256 + i] = 0.0f;
}

// ---------------------------------------------------------------------------
// fp16 hi/lo splits (elementwise)
// ---------------------------------------------------------------------------
__device__ __forceinline__ void split4h(float4 v, __half2* hi, __half2* lo, size_t idx2) {
    __half hx = __float2half_rn(v.x), hy = __float2half_rn(v.y);
    __half hz = __float2half_rn(v.z), hw = __float2half_rn(v.w);
    hi[idx2]     = __halves2half2(hx, hy);
    hi[idx2 + 1] = __halves2half2(hz, hw);
    lo[idx2]     = __halves2half2(__float2half_rn(v.x - __half2float(hx)),
                                  __float2half_rn(v.y - __half2float(hy)));
    lo[idx2 + 1] = __halves2half2(__float2half_rn(v.z - __half2float(hz)),
                                  __float2half_rn(v.w - __half2float(hw)));
}

__global__ __launch_bounds__(256) void k_splitE(const float* __restrict__ E) {
    const size_t i = (size_t)blockIdx.x * 256 + threadIdx.x;
    float4 v = ((const float4*)E)[i];
    split4h(v, (__half2*)g_Ehi, (__half2*)g_Elo, 2 * i);
}

__global__ __launch_bounds__(256) void k_splitH(const float* __restrict__ H) {
    const size_t i = (size_t)blockIdx.x * 256 + threadIdx.x;
    float4 v = ((const float4*)H)[i];
    split4h(v, (__half2*)g_Hhi, (__half2*)g_Hlo, 2 * i);
}

// ---------------------------------------------------------------------------
__global__ __launch_bounds__(256) void k_reduce() {
    const int i = blockIdx.x * 256 + threadIdx.x;
    const float4* P = (const float4*)g_part;
    float4 s = P[i];
#pragma unroll
    for (int p = 1; p < SPLITS; p++) {
        float4 v = P[(size_t)p * (BATCH * NSQ / 4) + i];
        s.x += v.x; s.y += v.y; s.z += v.z; s.w += v.w;
    }
    ((float4*)g_G)[i] = s;
}

__global__ __launch_bounds__(256) void k_colmean() {
    const int b = blockIdx.y;
    const int j = blockIdx.x * 32 + (threadIdx.x & 31);
    const int er = threadIdx.x >> 5;
    const float* G = g_G + b * NSQ;
    float s = 0.0f;
    for (int e = er; e < ENSN; e += 8) s += G[e * 256 + j];
    __shared__ float red[8][32];
    red[er][threadIdx.x & 31] = s;
    __syncthreads();
    if (er == 0) {
        float t = 0.0f;
#pragma unroll
        for (int r = 0; r < 8; r++) t += red[r][threadIdx.x & 31];
        g_mu[b * 256 + j] = t * (1.0f / 256.0f);
    }
}

__global__ __launch_bounds__(256) void k_centerT(const float* __restrict__ ymean,
                                                 const float* __restrict__ ystd,
                                                 const float* __restrict__ noise) {
    const int b = blockIdx.z, j0 = blockIdx.y * 32, e0 = blockIdx.x * 32;
    float* G = g_G + b * NSQ;
    float* Z = g_Z + b * NSQ;
    const float* nz = noise + b * NSQ;
    __shared__ float T[32][33];
    const int tx = threadIdx.x & 31, ty = threadIdx.x >> 5;
    const float mu = g_mu[b * 256 + j0 + tx];
#pragma unroll
    for (int r = 0; r < 4; r++) {
        const int e = e0 + ty + r * 8;
        float gc = G[e * 256 + j0 + tx] - mu;
        G[e * 256 + j0 + tx] = gc;
        T[ty + r * 8][tx] = gc;
    }
    __syncthreads();
#pragma unroll
    for (int r = 0; r < 4; r++) {
        const int j = j0 + ty + r * 8;
        const float ym = ymean[j];
        const float sd = ystd[j];
        Z[j * 256 + e0 + tx] = ym - T[tx][ty + r * 8] + nz[j * 256 + e0 + tx] * sd * sd;
    }
}

__global__ __launch_bounds__(256) void k_cyy(const float* __restrict__ ystd) {
    const int b = blockIdx.y;
    const int u0 = (blockIdx.x >> 2) * 64, v0 = (blockIdx.x & 3) * 64;
    const float* G = g_G + b * NSQ;
    float* A = g_A + b * NSQ;
    __shared__ float Us[16][64];
    __shared__ float Vs[16][64];
    const int tx = threadIdx.x & 15, ty = threadIdx.x >> 4;
    const int lk = threadIdx.x >> 4, lc = (threadIdx.x & 15) * 4;
    float acc[4][4];
#pragma unroll
    for (int i = 0; i < 4; i++)
#pragma unroll
        for (int j = 0; j < 4; j++) acc[i][j] = 0.0f;

    for (int ee = 0; ee < 256; ee += 16) {
        *(float4*)&Us[lk][lc] = *(const float4*)&G[(ee + lk) * 256 + u0 + lc];
        *(float4*)&Vs[lk][lc] = *(const float4*)&G[(ee + lk) * 256 + v0 + lc];
        __syncthreads();
#pragma unroll
        for (int k = 0; k < 16; k++) {
            float4 u = *(float4*)&Us[k][ty * 4];
            float4 v = *(float4*)&Vs[k][tx * 4];
            float ua[4] = {u.x, u.y, u.z, u.w};
            float va[4] = {v.x, v.y, v.z, v.w};
#pragma unroll
            for (int i = 0; i < 4; i++)
#pragma unroll
                for (int j = 0; j < 4; j++) acc[i][j] = fmaf(ua[i], va[j], acc[i][j]);
        }
        __syncthreads();
    }
#pragma unroll
    for (int i = 0; i < 4; i++)
#pragma unroll
        for (int j = 0; j < 4; j++) {
            const int u = u0 + ty * 4 + i, v = v0 + tx * 4 + j;
            float val = acc[i][j] * (1.0f / 256.0f);
            if (u == v) { float sd = ystd[u]; val += sd * sd; }
            A[u * 256 + v] = val;
        }
}

// ---------------------------------------------------------------------------
// Blocked Cholesky: panel in smem, trailing update in 4x4 register tiles
// ---------------------------------------------------------------------------
__global__ __launch_bounds__(256) void k_chol() {
    const int b = blockIdx.x;
    float* a = g_A + b * NSQ;
    __shared__ float P[256][33];
    __shared__ float sD[32];
    const int tid = threadIdx.x;

    for (int kb = 0; kb < 8; kb++) {
        const int j0 = kb * 32;
        if (tid >= j0) {
#pragma unroll
            for (int c = 0; c < 32; c++) P[tid][c] = a[tid * 256 + j0 + c];
        }
        __syncthreads();
        for (int k = 0; k < 32; k++) {
            const int gk = j0 + k;
            const float piv = P[gk][k];
            const float d = sqrtf(piv);
            const float rd = 1.0f / d;
            if (tid == gk) sD[k] = d;
            if (tid > gk) P[tid][k] *= rd;
            __syncthreads();
            if (tid > gk) {
                const float lrk = P[tid][k];
#pragma unroll
                for (int c = k + 1; c < 32; c++) P[tid][c] -= lrk * P[j0 + c][k];
            }
            __syncthreads();
        }
        if (tid >= j0) {
#pragma unroll
            for (int c = 0; c < 32; c++) {
                float val = P[tid][c];
                if (tid - j0 == c) val = sD[c];
                a[tid * 256 + j0 + c] = val;
            }
        }
        __syncthreads();
        // trailing update: 4x4 register tiles, float4 gmem, 8 LDS / 16 FMA per k
        const int rem = 224 - j0;
        if (rem > 0) {
            const int nt4 = rem >> 2;
            for (int t = tid; t < nt4 * nt4; t += 256) {
                const int ti = t / nt4, tj = t - ti * nt4;
                const int r0 = j0 + 32 + ti * 4, c0 = j0 + 32 + tj * 4;
                float4 acc[4];
#pragma unroll
                for (int i = 0; i < 4; i++)
                    acc[i] = *(float4*)&a[(r0 + i) * 256 + c0];
#pragma unroll
                for (int k = 0; k < 32; k++) {
                    float pr[4], pc[4];
#pragma unroll
                    for (int i = 0; i < 4; i++) { pr[i] = P[r0 + i][k]; pc[i] = P[c0 + i][k]; }
#pragma unroll
                    for (int i = 0; i < 4; i++) {
                        acc[i].x = fmaf(-pr[i], pc[0], acc[i].x);
                        acc[i].y = fmaf(-pr[i], pc[1], acc[i].y);
                        acc[i].z = fmaf(-pr[i], pc[2], acc[i].z);
                        acc[i].w = fmaf(-pr[i], pc[3], acc[i].w);
                    }
                }
#pragma unroll
                for (int i = 0; i < 4; i++)
                    *(float4*)&a[(r0 + i) * 256 + c0] = acc[i];
            }
        }
        __syncthreads();
    }
}

__global__ void k_invdiag() {
    const int p = blockIdx.x & 7, b = blockIdx.x >> 3, j0 = p * 32;
    const float* a = g_A + b * NSQ;
    __shared__ float Ld[32][33];
    __shared__ float Xc[32][33];
    const int lane = threadIdx.x;
    for (int i = 0; i < 32; i++) Ld[i][lane] = a[(j0 + i) * 256 + j0 + lane];
    __syncwarp();
    for (int i = 0; i < 32; i++) {
        float s = (i == lane) ? 1.0f : 0.0f;
        for (int k = lane; k < i; k++) s -= Ld[i][k] * Xc[k][lane];
        Xc[i][lane] = (i >= lane) ? s / Ld[i][i] : 0.0f;
    }
    __syncwarp();
    for (int i = 0; i < 32; i++)
        g_Dinv[(b * 8 + p) * 1024 + i * 32 + lane] = Xc[i][lane];
}

// ---------------------------------------------------------------------------
// Trisolve, register-cached Z panel
// ---------------------------------------------------------------------------
#define TS_SMEM 129920
__global__ __launch_bounds__(256) void k_trisolve2() {
    extern __shared__ float sm[];
    float (*Zs)[65] = (float(*)[65])sm;
    float (*Dv)[33] = (float(*)[33])(sm + 256 * 65);
    float (*Lp)[33] = (float(*)[33])(sm + 256 * 65 + 256 * 33);
    const int b = blockIdx.y, e0 = blockIdx.x * 64;
    const float* L = g_A + b * NSQ;
    float* Z = g_Z + b * NSQ;
    const int tid = threadIdx.x, c = tid & 63, rg = tid >> 6;

    for (int idx = tid; idx < 256 * 64; idx += 256)
        Zs[idx >> 6][idx & 63] = Z[(idx >> 6) * 256 + e0 + (idx & 63)];
    for (int idx = tid; idx < 8 * 32 * 32; idx += 256)
        Dv[idx >> 5][idx & 31] = g_Dinv[b * 8192 + idx];
    __syncthreads();

    for (int p = 0; p < 8; p++) {
        const int j0 = p * 32, rem = 224 - j0;
        float zr[32];
#pragma unroll
        for (int k = 0; k < 32; k++) zr[k] = Zs[j0 + k][c];
        float w[8];
#pragma unroll
        for (int q = 0; q < 8; q++) {
            const int r = rg * 8 + q;
            float s = 0.0f;
#pragma unroll
            for (int k = 0; k < 32; k++) s = fmaf(Dv[p * 32 + r][k], zr[k], s);
            w[q] = s;
        }
        for (int idx = tid; idx < rem * 32; idx += 256)
            Lp[idx >> 5][idx & 31] = L[(j0 + 32 + (idx >> 5)) * 256 + j0 + (idx & 31)];
        __syncthreads();
#pragma unroll
        for (int q = 0; q < 8; q++) Zs[j0 + rg * 8 + q][c] = w[q];
        __syncthreads();
#pragma unroll
        for (int k = 0; k < 32; k++) zr[k] = Zs[j0 + k][c];
        for (int rr = rg; rr < rem; rr += 4) {
            float acc = Zs[j0 + 32 + rr][c];
#pragma unroll
            for (int k = 0; k < 32; k++) acc = fmaf(-Lp[rr][k], zr[k], acc);
            Zs[j0 + 32 + rr][c] = acc;
        }
        __syncthreads();
    }

    for (int p = 7; p >= 0; p--) {
        const int j0 = p * 32;
        float zr[32];
#pragma unroll
        for (int i = 0; i < 32; i++) zr[i] = Zs[j0 + i][c];
        float w[8];
#pragma unroll
        for (int q = 0; q < 8; q++) {
            const int k = rg * 8 + q;
            float s = 0.0f;
#pragma unroll
            for (int i = 0; i < 32; i++) s = fmaf(Dv[p * 32 + i][k], zr[i], s);
            w[q] = s;
        }
        for (int idx = tid; idx < j0 * 32; idx += 256)
            Lp[idx >> 5][idx & 31] = L[(j0 + (idx & 31)) * 256 + (idx >> 5)];
        __syncthreads();
#pragma unroll
        for (int q = 0; q < 8; q++) Zs[j0 + rg * 8 + q][c] = w[q];
        __syncthreads();
#pragma unroll
        for (int k = 0; k < 32; k++) zr[k] = Zs[j0 + k][c];
        for (int t = rg; t < j0; t += 4) {
            float acc = Zs[t][c];
#pragma unroll
            for (int k = 0; k < 32; k++) acc = fmaf(-Lp[t][k], zr[k], acc);
            Zs[t][c] = acc;
        }
        __syncthreads();
    }

    for (int idx = tid; idx < 256 * 64; idx += 256)
        Z[(idx >> 6) * 256 + e0 + (idx & 63)] = Zs[idx >> 6][idx & 63];
}

// W'[e][f] = (e==f) + (1/ens) sum_j Z[j][e] * Gc[f][j]  -> fp16 hi/lo
__global__ __launch_bounds__(256) void k_wp() {
    const int b = blockIdx.y;
    const int e0 = (blockIdx.x >> 2) * 64, f0 = (blockIdx.x & 3) * 64;
    const float* G = g_G + b * NSQ;
    const float* Z = g_Z + b * NSQ;
    __shared__ float sZ[16][64];
    __shared__ float sG[16][64];
    const int tx = threadIdx.x & 15, ty = threadIdx.x >> 4;
    const int lk = threadIdx.x >> 4, lc = (threadIdx.x & 15) * 4;
    const int gn = threadIdx.x >> 2, gk = (threadIdx.x & 3) * 4;
    float acc[4][4];
#pragma unroll
    for (int i = 0; i < 4; i++)
#pragma unroll
        for (int j = 0; j < 4; j++) acc[i][j] = 0.0f;

    for (int jj = 0; jj < 256; jj += 16) {
        *(float4*)&sZ[lk][lc] = *(const float4*)&Z[(jj + lk) * 256 + e0 + lc];
        float4 gv = *(const float4*)&G[(f0 + gn) * 256 + jj + gk];
        sG[gk + 0][gn] = gv.x; sG[gk + 1][gn] = gv.y;
        sG[gk + 2][gn] = gv.z; sG[gk + 3][gn] = gv.w;
        __syncthreads();
#pragma unroll
        for (int k = 0; k < 16; k++) {
            float4 zv = *(float4*)&sZ[k][ty * 4];
            float4 gg = *(float4*)&sG[k][tx * 4];
            float za[4] = {zv.x, zv.y, zv.z, zv.w};
            float ga[4] = {gg.x, gg.y, gg.z, gg.w};
#pragma unroll
            for (int i = 0; i < 4; i++)
#pragma unroll
                for (int j = 0; j < 4; j++) acc[i][j] = fmaf(za[i], ga[j], acc[i][j]);
        }
        __syncthreads();
    }
#pragma unroll
    for (int i = 0; i < 4; i++)
#pragma unroll
        for (int j = 0; j < 4; j++) {
            const int e = e0 + ty * 4 + i, f = f0 + tx * 4 + j;
            float val = acc[i][j] * (1.0f / 256.0f);
            if (e == f) val += 1.0f;              // fold identity into W'
            __half h = __float2half_rn(val);
            g_Whi[b * NSQ + e * 256 + f] = h;
            g_Wlo[b * NSQ + e * 256 + f] = __float2half_rn(val - __half2float(h));
        }
}

// ---------------------------------------------------------------------------
extern "C" void kernel_launch(void* const* d_in, const int* in_sizes, int n_in,
                              void* d_out, int out_size) {
    const float* E     = (const float*)d_in[0];
    const float* H     = (const float*)d_in[1];
    const float* ymean = (const float*)d_in[2];
    const float* ystd  = (const float*)d_in[3];
    const float* noise = (const float*)d_in[4];
    float* out = (float*)d_out;

    cudaFuncSetAttribute(k_mm1, cudaFuncAttributeMaxDynamicSharedMemorySize, GSMEM);
    cudaFuncSetAttribute(k_mm3, cudaFuncAttributeMaxDynamicSharedMemorySize, GSMEM);
    cudaFuncSetAttribute(k_trisolve2, cudaFuncAttributeMaxDynamicSharedMemorySize, TS_SMEM);

    k_dummy<<<1, 256>>>();                                  // idx 0
    k_splitH<<<2048, 256>>>(H);                             // idx 1
    k_splitE<<<16384, 256>>>(E);                            // idx 2
    k_mm1<<<dim3(4, SPLITS, BATCH), 256, GSMEM>>>();        // idx 3  <- ncu capture
    k_reduce<<<(BATCH * NSQ / 4) / 256, 256>>>();
    k_colmean<<<dim3(8, BATCH), 256>>>();
    k_centerT<<<dim3(8, 8, BATCH), 256>>>(ymean, ystd, noise);
    k_cyy<<<dim3(16, BATCH), 256>>>(ystd);
    k_chol<<<BATCH, 256>>>();
    k_invdiag<<<64, 32>>>();
    k_trisolve2<<<dim3(4, BATCH), 256, TS_SMEM>>>();
    k_wp<<<dim3(16, BATCH), 256>>>();
    k_mm3<<<dim3(64, 2, BATCH), 256, GSMEM>>>(out);
}

// round 12
// speedup vs baseline: 1.7980x; 1.0019x over previous
#include <cuda_runtime.h>
#include <cuda_fp16.h>
#include <cstdint>

// EnsKF step. fp16 3-term split mma GEMMs (term-major MMA order) +
// reg-blocked chol + reg-cached trisolve.
//   G  = E @ H;  Gc = G - colmean;  A = Gc^T Gc/ens + diag(std^2);  L = chol(A)
//   Dinv = inv of L's 32x32 diag blocks;  Z = A^{-1} innov
//   W' = I + (1/ens)(Gc @ Z)^T  -> fp16 hi/lo
//   out = W' @ E

#define BATCH 8
#define ENSN  256
#define XDIM  8192
#define NSQ   65536
#define SPLITS 8

__device__ __align__(256) float g_part[SPLITS * BATCH * NSQ];
__device__ __align__(256) float g_G[BATCH * NSQ];
__device__ __align__(256) float g_mu[BATCH * 256];
__device__ __align__(256) float g_A[BATCH * NSQ];
__device__ __align__(256) float g_Z[BATCH * NSQ];
__device__ __align__(256) float g_Dinv[BATCH * 8 * 32 * 32];
__device__ __align__(256) __half g_Ehi[BATCH * ENSN * XDIM];
__device__ __align__(256) __half g_Elo[BATCH * ENSN * XDIM];
__device__ __align__(256) __half g_Hhi[XDIM * 256];
__device__ __align__(256) __half g_Hlo[XDIM * 256];
__device__ __align__(256) __half g_Whi[BATCH * NSQ];
__device__ __align__(256) __half g_Wlo[BATCH * NSQ];

// ---------------- smem layout (bytes) ----------------
#define SM_A(buf, hl) ((buf) * 20480 + (hl) * 10240)
#define SM_B(buf, hl) (40960 + (buf) * 17408 + (hl) * 8704)
#define GSMEM (40960 + 34816)

// ---------------- low-level helpers ----------------
__device__ __forceinline__ uint32_t smem_u32(const void* p) {
    uint32_t a;
    asm("{ .reg .u64 t; cvta.to.shared.u64 t, %1; cvt.u32.u64 %0, t; }" : "=r"(a) : "l"(p));
    return a;
}
__device__ __forceinline__ void cpa16(uint32_t dst, const void* src) {
    asm volatile("cp.async.cg.shared.global [%0], [%1], 16;" :: "r"(dst), "l"(src));
}
__device__ __forceinline__ void ldsm4(uint32_t* r, uint32_t a) {
    asm volatile("ldmatrix.sync.aligned.m8n8.x4.shared.b16 {%0,%1,%2,%3}, [%4];"
                 : "=r"(r[0]), "=r"(r[1]), "=r"(r[2]), "=r"(r[3]) : "r"(a));
}
__device__ __forceinline__ void ldsm4t(uint32_t* r, uint32_t a) {
    asm volatile("ldmatrix.sync.aligned.m8n8.x4.trans.shared.b16 {%0,%1,%2,%3}, [%4];"
                 : "=r"(r[0]), "=r"(r[1]), "=r"(r[2]), "=r"(r[3]) : "r"(a));
}
__device__ __forceinline__ void mma16816(float* c, const uint32_t* a, const uint32_t* b) {
    asm volatile("mma.sync.aligned.m16n8k16.row.col.f32.f16.f16.f32 "
                 "{%0,%1,%2,%3},{%4,%5,%6,%7},{%8,%9},{%0,%1,%2,%3};"
                 : "+f"(c[0]), "+f"(c[1]), "+f"(c[2]), "+f"(c[3])
                 : "r"(a[0]), "r"(a[1]), "r"(a[2]), "r"(a[3]), "r"(b[0]), "r"(b[1]));
}

// ---------------- tile producers ----------------
__device__ __forceinline__ void issue_tiles(
    uint32_t sb, int buf,
    const __half* __restrict__ Ahi, const __half* __restrict__ Alo, size_t lda,
    const __half* __restrict__ Bhi, const __half* __restrict__ Blo, size_t ldb,
    int kbase, int tid)
{
#pragma unroll
    for (int half_ = 0; half_ < 2; half_++) {
        const __half* src = half_ ? Alo : Ahi;
#pragma unroll
        for (int it = 0; it < 2; it++) {
            const int i = tid + it * 256;
            const int r = i >> 2, seg = i & 3;
            cpa16(sb + SM_A(buf, half_) + r * 80 + seg * 16,
                  src + (size_t)r * lda + kbase + seg * 8);
        }
    }
#pragma unroll
    for (int half_ = 0; half_ < 2; half_++) {
        const __half* src = half_ ? Blo : Bhi;
#pragma unroll
        for (int it = 0; it < 2; it++) {
            const int i = tid + it * 256;
            const int r = i >> 4, seg = i & 15;
            cpa16(sb + SM_B(buf, half_) + r * 272 + seg * 16,
                  src + (size_t)(kbase + r) * ldb + seg * 8);
        }
    }
}

// ---------------- warp compute: one 32-K chunk, 3-term fp16 split ----------------
// Term-major MMA order: consecutive MMAs touch 4 different accumulators
// (chain distance 4) instead of re-hitting the same accumulator 3x.
__device__ __forceinline__ void compute_chunk(uint32_t sb, int buf, int lane,
                                              int wm, int wn, float acc[4][4][4]) {
    const int arow = lane & 15, aoff = (lane >> 4) * 16;
    const int brow = (lane & 7) + ((lane >> 3) & 1) * 8, boff = (lane >> 4) * 16;
#pragma unroll
    for (int k16 = 0; k16 < 2; k16++) {
        uint32_t bh[2][4], bl[2][4];
#pragma unroll
        for (int nj = 0; nj < 2; nj++) {
            ldsm4t(bh[nj], sb + SM_B(buf, 0) + (k16 * 16 + brow) * 272 + (wn + nj * 16) * 2 + boff);
            ldsm4t(bl[nj], sb + SM_B(buf, 1) + (k16 * 16 + brow) * 272 + (wn + nj * 16) * 2 + boff);
        }
#pragma unroll
        for (int mi = 0; mi < 4; mi++) {
            uint32_t ah[4], al[4];
            ldsm4(ah, sb + SM_A(buf, 0) + (wm + 16 * mi + arow) * 80 + k16 * 32 + aoff);
            ldsm4(al, sb + SM_A(buf, 1) + (wm + 16 * mi + arow) * 80 + k16 * 32 + aoff);
#pragma unroll
            for (int n8 = 0; n8 < 4; n8++)
                mma16816(acc[mi][n8], ah, &bh[n8 >> 1][(n8 & 1) * 2]);
#pragma unroll
            for (int n8 = 0; n8 < 4; n8++)
                mma16816(acc[mi][n8], ah, &bl[n8 >> 1][(n8 & 1) * 2]);
#pragma unroll
            for (int n8 = 0; n8 < 4; n8++)
                mma16816(acc[mi][n8], al, &bh[n8 >> 1][(n8 & 1) * 2]);
        }
    }
}

// ---------------- main accumulate driver (128m x 128n CTA) ----------------
__device__ __forceinline__ void mm_main(
    const __half* Ahi, const __half* Alo, size_t lda,
    const __half* Bhi, const __half* Blo, size_t ldb,
    int nch, float acc[4][4][4], char* smem)
{
    const uint32_t sb = smem_u32(smem);
    const int tid = threadIdx.x, lane = tid & 31, w = tid >> 5;
    const int wm = (w & 1) * 64, wn = (w >> 1) * 32;
#pragma unroll
    for (int i = 0; i < 4; i++)
#pragma unroll
        for (int j = 0; j < 4; j++)
#pragma unroll
            for (int q = 0; q < 4; q++) acc[i][j][q] = 0.0f;

    issue_tiles(sb, 0, Ahi, Alo, lda, Bhi, Blo, ldb, 0, tid);
    asm volatile("cp.async.commit_group;" ::: "memory");
    issue_tiles(sb, 1, Ahi, Alo, lda, Bhi, Blo, ldb, 32, tid);
    asm volatile("cp.async.commit_group;" ::: "memory");

    for (int c = 0; c < nch; c++) {
        asm volatile("cp.async.wait_group 1;" ::: "memory");
        __syncthreads();
        compute_chunk(sb, c & 1, lane, wm, wn, acc);
        __syncthreads();
        if (c + 2 < nch)
            issue_tiles(sb, c & 1, Ahi, Alo, lda, Bhi, Blo, ldb, (c + 2) * 32, tid);
        asm volatile("cp.async.commit_group;" ::: "memory");
    }
}

// ---------------------------------------------------------------------------
// GEMM1: split-K partials of G = E @ H.  grid(4 = mt*2+nt, 8 splits, 8 b)
// ---------------------------------------------------------------------------
__global__ __launch_bounds__(256, 2) void k_mm1() {
    extern __shared__ char smem[];
    const int mt = blockIdx.x >> 1, nt = blockIdx.x & 1;
    const int s = blockIdx.y, b = blockIdx.z;
    const size_t aoff = ((size_t)b * ENSN + mt * 128) * XDIM + (size_t)s * 1024;
    const size_t boff = (size_t)(s * 1024) * 256 + nt * 128;
    float acc[4][4][4];
    mm_main(g_Ehi + aoff, g_Elo + aoff, XDIM, g_Hhi + boff, g_Hlo + boff, 256, 32, acc, smem);

    float* Cp = g_part + (size_t)(s * BATCH + b) * NSQ + (mt * 128) * 256 + nt * 128;
    const int lane = threadIdx.x & 31, w = threadIdx.x >> 5;
    const int wm = (w & 1) * 64, wn = (w >> 1) * 32;
#pragma unroll
    for (int mi = 0; mi < 4; mi++)
#pragma unroll
        for (int n8 = 0; n8 < 4; n8++) {
            const int r = wm + 16 * mi + (lane >> 2);
            const int cc = wn + n8 * 8 + (lane & 3) * 2;
            *(float2*)(Cp + r * 256 + cc) = make_float2(acc[mi][n8][0], acc[mi][n8][1]);
            *(float2*)(Cp + (r + 8) * 256 + cc) = make_float2(acc[mi][n8][2], acc[mi][n8][3]);
        }
}

// ---------------------------------------------------------------------------
// GEMM3: out = W' @ E.  grid(64 nt, 2 mt, 8 b)
// ---------------------------------------------------------------------------
__global__ __launch_bounds__(256, 2) void k_mm3(float* __restrict__ out) {
    extern __shared__ char smem[];
    const int nt = blockIdx.x, mt = blockIdx.y, b = blockIdx.z;
    const int n0 = nt * 128;
    const size_t aoff = (size_t)b * NSQ + (size_t)(mt * 128) * 256;
    const size_t boff = (size_t)b * ENSN * XDIM + n0;
    float acc[4][4][4];
    mm_main(g_Whi + aoff, g_Wlo + aoff, 256, g_Ehi + boff, g_Elo + boff, XDIM, 8, acc, smem);

    const int lane = threadIdx.x & 31, w = threadIdx.x >> 5;
    const int wm = (w & 1) * 64, wn = (w >> 1) * 32;
    float* Op = out + (size_t)b * ENSN * XDIM;
#pragma unroll
    for (int mi = 0; mi < 4; mi++)
#pragma unroll
        for (int n8 = 0; n8 < 4; n8++) {
            const int e = mt * 128 + wm + 16 * mi + (lane >> 2);
            const int x = n0 + wn + n8 * 8 + (lane & 3) * 2;
            *(float2*)(Op + (size_t)e * XDIM + x) =
                make_float2(acc[mi][n8][0], acc[mi][n8][1]);
            *(float2*)(Op + (size_t)(e + 8) * XDIM + x) =
                make_float2(acc[mi][n8][2], acc[mi][n8][3]);
        }
}

// ---------------------------------------------------------------------------
// Dummy at launch index 0 so ncu (captures index 3) profiles k_mm1.
// ---------------------------------------------------------------------------
__global__ void k_dummy() {
    const int i = threadIdx.x;
#pragma unroll
    for (int r = 0; r < 8; r++) g_mu[r * 256 + i] = 0.0f;
}

// ---------------------------------------------------------------------------
// fp16 hi/lo splits (elementwise)
// ---------------------------------------------------------------------------
__device__ __forceinline__ void split4h(float4 v, __half2* hi, __half2* lo, size_t idx2) {
    __half hx = __float2half_rn(v.x), hy = __float2half_rn(v.y);
    __half hz = __float2half_rn(v.z), hw = __float2half_rn(v.w);
    hi[idx2]     = __halves2half2(hx, hy);
    hi[idx2 + 1] = __halves2half2(hz, hw);
    lo[idx2]     = __halves2half2(__float2half_rn(v.x - __half2float(hx)),
                                  __float2half_rn(v.y - __half2float(hy)));
    lo[idx2 + 1] = __halves2half2(__float2half_rn(v.z - __half2float(hz)),
                                  __float2half_rn(v.w - __half2float(hw)));
}

__global__ __launch_bounds__(256) void k_splitE(const float* __restrict__ E) {
    const size_t i = (size_t)blockIdx.x * 256 + threadIdx.x;
    float4 v = ((const float4*)E)[i];
    split4h(v, (__half2*)g_Ehi, (__half2*)g_Elo, 2 * i);
}

__global__ __launch_bounds__(256) void k_splitH(const float* __restrict__ H) {
    const size_t i = (size_t)blockIdx.x * 256 + threadIdx.x;
    float4 v = ((const float4*)H)[i];
    split4h(v, (__half2*)g_Hhi, (__half2*)g_Hlo, 2 * i);
}

// ---------------------------------------------------------------------------
__global__ __launch_bounds__(256) void k_reduce() {
    const int i = blockIdx.x * 256 + threadIdx.x;
    const float4* P = (const float4*)g_part;
    float4 s = P[i];
#pragma unroll
    for (int p = 1; p < SPLITS; p++) {
        float4 v = P[(size_t)p * (BATCH * NSQ / 4) + i];
        s.x += v.x; s.y += v.y; s.z += v.z; s.w += v.w;
    }
    ((float4*)g_G)[i] = s;
}

__global__ __launch_bounds__(256) void k_colmean() {
    const int b = blockIdx.y;
    const int j = blockIdx.x * 32 + (threadIdx.x & 31);
    const int er = threadIdx.x >> 5;
    const float* G = g_G + b * NSQ;
    float s = 0.0f;
    for (int e = er; e < ENSN; e += 8) s += G[e * 256 + j];
    __shared__ float red[8][32];
    red[er][threadIdx.x & 31] = s;
    __syncthreads();
    if (er == 0) {
        float t = 0.0f;
#pragma unroll
        for (int r = 0; r < 8; r++) t += red[r][threadIdx.x & 31];
        g_mu[b * 256 + j] = t * (1.0f / 256.0f);
    }
}

__global__ __launch_bounds__(256) void k_centerT(const float* __restrict__ ymean,
                                                 const float* __restrict__ ystd,
                                                 const float* __restrict__ noise) {
    const int b = blockIdx.z, j0 = blockIdx.y * 32, e0 = blockIdx.x * 32;
    float* G = g_G + b * NSQ;
    float* Z = g_Z + b * NSQ;
    const float* nz = noise + b * NSQ;
    __shared__ float T[32][33];
    const int tx = threadIdx.x & 31, ty = threadIdx.x >> 5;
    const float mu = g_mu[b * 256 + j0 + tx];
#pragma unroll
    for (int r = 0; r < 4; r++) {
        const int e = e0 + ty + r * 8;
        float gc = G[e * 256 + j0 + tx] - mu;
        G[e * 256 + j0 + tx] = gc;
        T[ty + r * 8][tx] = gc;
    }
    __syncthreads();
#pragma unroll
    for (int r = 0; r < 4; r++) {
        const int j = j0 + ty + r * 8;
        const float ym = ymean[j];
        const float sd = ystd[j];
        Z[j * 256 + e0 + tx] = ym - T[tx][ty + r * 8] + nz[j * 256 + e0 + tx] * sd * sd;
    }
}

__global__ __launch_bounds__(256) void k_cyy(const float* __restrict__ ystd) {
    const int b = blockIdx.y;
    const int u0 = (blockIdx.x >> 2) * 64, v0 = (blockIdx.x & 3) * 64;
    const float* G = g_G + b * NSQ;
    float* A = g_A + b * NSQ;
    __shared__ float Us[16][64];
    __shared__ float Vs[16][64];
    const int tx = threadIdx.x & 15, ty = threadIdx.x >> 4;
    const int lk = threadIdx.x >> 4, lc = (threadIdx.x & 15) * 4;
    float acc[4][4];
#pragma unroll
    for (int i = 0; i < 4; i++)
#pragma unroll
        for (int j = 0; j < 4; j++) acc[i][j] = 0.0f;

    for (int ee = 0; ee < 256; ee += 16) {
        *(float4*)&Us[lk][lc] = *(const float4*)&G[(ee + lk) * 256 + u0 + lc];
        *(float4*)&Vs[lk][lc] = *(const float4*)&G[(ee + lk) * 256 + v0 + lc];
        __syncthreads();
#pragma unroll
        for (int k = 0; k < 16; k++) {
            float4 u = *(float4*)&Us[k][ty * 4];
            float4 v = *(float4*)&Vs[k][tx * 4];
            float ua[4] = {u.x, u.y, u.z, u.w};
            float va[4] = {v.x, v.y, v.z, v.w};
#pragma unroll
            for (int i = 0; i < 4; i++)
#pragma unroll
                for (int j = 0; j < 4; j++) acc[i][j] = fmaf(ua[i], va[j], acc[i][j]);
        }
        __syncthreads();
    }
#pragma unroll
    for (int i = 0; i < 4; i++)
#pragma unroll
        for (int j = 0; j < 4; j++) {
            const int u = u0 + ty * 4 + i, v = v0 + tx * 4 + j;
            float val = acc[i][j] * (1.0f / 256.0f);
            if (u == v) { float sd = ystd[u]; val += sd * sd; }
            A[u * 256 + v] = val;
        }
}

// ---------------------------------------------------------------------------
// Blocked Cholesky: panel in smem, trailing update in 4x4 register tiles
// ---------------------------------------------------------------------------
__global__ __launch_bounds__(256) void k_chol() {
    const int b = blockIdx.x;
    float* a = g_A + b * NSQ;
    __shared__ float P[256][33];
    __shared__ float sD[32];
    const int tid = threadIdx.x;

    for (int kb = 0; kb < 8; kb++) {
        const int j0 = kb * 32;
        if (tid >= j0) {
#pragma unroll
            for (int c = 0; c < 32; c++) P[tid][c] = a[tid * 256 + j0 + c];
        }
        __syncthreads();
        for (int k = 0; k < 32; k++) {
            const int gk = j0 + k;
            const float piv = P[gk][k];
            const float d = sqrtf(piv);
            const float rd = 1.0f / d;
            if (tid == gk) sD[k] = d;
            if (tid > gk) P[tid][k] *= rd;
            __syncthreads();
            if (tid > gk) {
                const float lrk = P[tid][k];
#pragma unroll
                for (int c = k + 1; c < 32; c++) P[tid][c] -= lrk * P[j0 + c][k];
            }
            __syncthreads();
        }
        if (tid >= j0) {
#pragma unroll
            for (int c = 0; c < 32; c++) {
                float val = P[tid][c];
                if (tid - j0 == c) val = sD[c];
                a[tid * 256 + j0 + c] = val;
            }
        }
        __syncthreads();
        const int rem = 224 - j0;
        if (rem > 0) {
            const int nt4 = rem >> 2;
            for (int t = tid; t < nt4 * nt4; t += 256) {
                const int ti = t / nt4, tj = t - ti * nt4;
                const int r0 = j0 + 32 + ti * 4, c0 = j0 + 32 + tj * 4;
                float4 acc[4];
#pragma unroll
                for (int i = 0; i < 4; i++)
                    acc[i] = *(float4*)&a[(r0 + i) * 256 + c0];
#pragma unroll
                for (int k = 0; k < 32; k++) {
                    float pr[4], pc[4];
#pragma unroll
                    for (int i = 0; i < 4; i++) { pr[i] = P[r0 + i][k]; pc[i] = P[c0 + i][k]; }
#pragma unroll
                    for (int i = 0; i < 4; i++) {
                        acc[i].x = fmaf(-pr[i], pc[0], acc[i].x);
                        acc[i].y = fmaf(-pr[i], pc[1], acc[i].y);
                        acc[i].z = fmaf(-pr[i], pc[2], acc[i].z);
                        acc[i].w = fmaf(-pr[i], pc[3], acc[i].w);
                    }
                }
#pragma unroll
                for (int i = 0; i < 4; i++)
                    *(float4*)&a[(r0 + i) * 256 + c0] = acc[i];
            }
        }
        __syncthreads();
    }
}

__global__ void k_invdiag() {
    const int p = blockIdx.x & 7, b = blockIdx.x >> 3, j0 = p * 32;
    const float* a = g_A + b * NSQ;
    __shared__ float Ld[32][33];
    __shared__ float Xc[32][33];
    const int lane = threadIdx.x;
    for (int i = 0; i < 32; i++) Ld[i][lane] = a[(j0 + i) * 256 + j0 + lane];
    __syncwarp();
    for (int i = 0; i < 32; i++) {
        float s = (i == lane) ? 1.0f : 0.0f;
        for (int k = lane; k < i; k++) s -= Ld[i][k] * Xc[k][lane];
        Xc[i][lane] = (i >= lane) ? s / Ld[i][i] : 0.0f;
    }
    __syncwarp();
    for (int i = 0; i < 32; i++)
        g_Dinv[(b * 8 + p) * 1024 + i * 32 + lane] = Xc[i][lane];
}

// ---------------------------------------------------------------------------
// Trisolve, register-cached Z panel
// ---------------------------------------------------------------------------
#define TS_SMEM 129920
__global__ __launch_bounds__(256) void k_trisolve2() {
    extern __shared__ float sm[];
    float (*Zs)[65] = (float(*)[65])sm;
    float (*Dv)[33] = (float(*)[33])(sm + 256 * 65);
    float (*Lp)[33] = (float(*)[33])(sm + 256 * 65 + 256 * 33);
    const int b = blockIdx.y, e0 = blockIdx.x * 64;
    const float* L = g_A + b * NSQ;
    float* Z = g_Z + b * NSQ;
    const int tid = threadIdx.x, c = tid & 63, rg = tid >> 6;

    for (int idx = tid; idx < 256 * 64; idx += 256)
        Zs[idx >> 6][idx & 63] = Z[(idx >> 6) * 256 + e0 + (idx & 63)];
    for (int idx = tid; idx < 8 * 32 * 32; idx += 256)
        Dv[idx >> 5][idx & 31] = g_Dinv[b * 8192 + idx];
    __syncthreads();

    for (int p = 0; p < 8; p++) {
        const int j0 = p * 32, rem = 224 - j0;
        float zr[32];
#pragma unroll
        for (int k = 0; k < 32; k++) zr[k] = Zs[j0 + k][c];
        float w[8];
#pragma unroll
        for (int q = 0; q < 8; q++) {
            const int r = rg * 8 + q;
            float s = 0.0f;
#pragma unroll
            for (int k = 0; k < 32; k++) s = fmaf(Dv[p * 32 + r][k], zr[k], s);
            w[q] = s;
        }
        for (int idx = tid; idx < rem * 32; idx += 256)
            Lp[idx >> 5][idx & 31] = L[(j0 + 32 + (idx >> 5)) * 256 + j0 + (idx & 31)];
        __syncthreads();
#pragma unroll
        for (int q = 0; q < 8; q++) Zs[j0 + rg * 8 + q][c] = w[q];
        __syncthreads();
#pragma unroll
        for (int k = 0; k < 32; k++) zr[k] = Zs[j0 + k][c];
        for (int rr = rg; rr < rem; rr += 4) {
            float acc = Zs[j0 + 32 + rr][c];
#pragma unroll
            for (int k = 0; k < 32; k++) acc = fmaf(-Lp[rr][k], zr[k], acc);
            Zs[j0 + 32 + rr][c] = acc;
        }
        __syncthreads();
    }

    for (int p = 7; p >= 0; p--) {
        const int j0 = p * 32;
        float zr[32];
#pragma unroll
        for (int i = 0; i < 32; i++) zr[i] = Zs[j0 + i][c];
        float w[8];
#pragma unroll
        for (int q = 0; q < 8; q++) {
            const int k = rg * 8 + q;
            float s = 0.0f;
#pragma unroll
            for (int i = 0; i < 32; i++) s = fmaf(Dv[p * 32 + i][k], zr[i], s);
            w[q] = s;
        }
        for (int idx = tid; idx < j0 * 32; idx += 256)
            Lp[idx >> 5][idx & 31] = L[(j0 + (idx & 31)) * 256 + (idx >> 5)];
        __syncthreads();
#pragma unroll
        for (int q = 0; q < 8; q++) Zs[j0 + rg * 8 + q][c] = w[q];
        __syncthreads();
#pragma unroll
        for (int k = 0; k < 32; k++) zr[k] = Zs[j0 + k][c];
        for (int t = rg; t < j0; t += 4) {
            float acc = Zs[t][c];
#pragma unroll
            for (int k = 0; k < 32; k++) acc = fmaf(-Lp[t][k], zr[k], acc);
            Zs[t][c] = acc;
        }
        __syncthreads();
    }

    for (int idx = tid; idx < 256 * 64; idx += 256)
        Z[(idx >> 6) * 256 + e0 + (idx & 63)] = Zs[idx >> 6][idx & 63];
}

// W'[e][f] = (e==f) + (1/ens) sum_j Z[j][e] * Gc[f][j]  -> fp16 hi/lo
__global__ __launch_bounds__(256) void k_wp() {
    const int b = blockIdx.y;
    const int e0 = (blockIdx.x >> 2) * 64, f0 = (blockIdx.x & 3) * 64;
    const float* G = g_G + b * NSQ;
    const float* Z = g_Z + b * NSQ;
    __shared__ float sZ[16][64];
    __shared__ float sG[16][64];
    const int tx = threadIdx.x & 15, ty = threadIdx.x >> 4;
    const int lk = threadIdx.x >> 4, lc = (threadIdx.x & 15) * 4;
    const int gn = threadIdx.x >> 2, gk = (threadIdx.x & 3) * 4;
    float acc[4][4];
#pragma unroll
    for (int i = 0; i < 4; i++)
#pragma unroll
        for (int j = 0; j < 4; j++) acc[i][j] = 0.0f;

    for (int jj = 0; jj < 256; jj += 16) {
        *(float4*)&sZ[lk][lc] = *(const float4*)&Z[(jj + lk) * 256 + e0 + lc];
        float4 gv = *(const float4*)&G[(f0 + gn) * 256 + jj + gk];
        sG[gk + 0][gn] = gv.x; sG[gk + 1][gn] = gv.y;
        sG[gk + 2][gn] = gv.z; sG[gk + 3][gn] = gv.w;
        __syncthreads();
#pragma unroll
        for (int k = 0; k < 16; k++) {
            float4 zv = *(float4*)&sZ[k][ty * 4];
            float4 gg = *(float4*)&sG[k][tx * 4];
            float za[4] = {zv.x, zv.y, zv.z, zv.w};
            float ga[4] = {gg.x, gg.y, gg.z, gg.w};
#pragma unroll
            for (int i = 0; i < 4; i++)
#pragma unroll
                for (int j = 0; j < 4; j++) acc[i][j] = fmaf(za[i], ga[j], acc[i][j]);
        }
        __syncthreads();
    }
#pragma unroll
    for (int i = 0; i < 4; i++)
#pragma unroll
        for (int j = 0; j < 4; j++) {
            const int e = e0 + ty * 4 + i, f = f0 + tx * 4 + j;
            float val = acc[i][j] * (1.0f / 256.0f);
            if (e == f) val += 1.0f;
            __half h = __float2half_rn(val);
            g_Whi[b * NSQ + e * 256 + f] = h;
            g_Wlo[b * NSQ + e * 256 + f] = __float2half_rn(val - __half2float(h));
        }
}

// ---------------------------------------------------------------------------
extern "C" void kernel_launch(void* const* d_in, const int* in_sizes, int n_in,
                              void* d_out, int out_size) {
    const float* E     = (const float*)d_in[0];
    const float* H     = (const float*)d_in[1];
    const float* ymean = (const float*)d_in[2];
    const float* ystd  = (const float*)d_in[3];
    const float* noise = (const float*)d_in[4];
    float* out = (float*)d_out;

    cudaFuncSetAttribute(k_mm1, cudaFuncAttributeMaxDynamicSharedMemorySize, GSMEM);
    cudaFuncSetAttribute(k_mm3, cudaFuncAttributeMaxDynamicSharedMemorySize, GSMEM);
    cudaFuncSetAttribute(k_trisolve2, cudaFuncAttributeMaxDynamicSharedMemorySize, TS_SMEM);

    k_dummy<<<1, 256>>>();                                  // idx 0
    k_splitH<<<2048, 256>>>(H);                             // idx 1
    k_splitE<<<16384, 256>>>(E);                            // idx 2
    k_mm1<<<dim3(4, SPLITS, BATCH), 256, GSMEM>>>();        // idx 3  <- ncu capture
    k_reduce<<<(BATCH * NSQ / 4) / 256, 256>>>();
    k_colmean<<<dim3(8, BATCH), 256>>>();
    k_centerT<<<dim3(8, 8, BATCH), 256>>>(ymean, ystd, noise);
    k_cyy<<<dim3(16, BATCH), 256>>>(ystd);
    k_chol<<<BATCH, 256>>>();
    k_invdiag<<<64, 32>>>();
    k_trisolve2<<<dim3(4, BATCH), 256, TS_SMEM>>>();
    k_wp<<<dim3(16, BATCH), 256>>>();
    k_mm3<<<dim3(64, 2, BATCH), 256, GSMEM>>>(out);
}